// round 10
// baseline (speedup 1.0000x reference)
#include <cuda_runtime.h>
#include <cuda_fp16.h>
#include <cstdint>

#define BB 4
#define CC 384
#define QQ 384
#define HH 256
#define KK 256

#define ST 40   // smem row stride in halves (80B): fragment LDS conflict-free

// ---------------------------------------------------------------- scratch
__device__ float g_term_h[BB*CC*KK];                 // term_h + b1 (exact fp32)
__device__ float g_term_u[BB*QQ*KK];                 // term_u     (exact fp32)
__device__ __align__(16) __half g_whu_h[KK*HH];      // W_hu fp16, [k][h] dense

__device__ __forceinline__ float lrelu(float x) {
    return fmaxf(x, 0.f) + 0.01f * fminf(x, 0.f);
}
// fp16-accumulator MMA: D(2regs) = A(4) * B(2) + C(2)
__device__ __forceinline__ void mma16h(uint32_t* d, const uint32_t* a, uint32_t b0, uint32_t b1) {
    asm volatile("mma.sync.aligned.m16n8k16.row.col.f16.f16.f16.f16 "
                 "{%0,%1}, {%2,%3,%4,%5}, {%6,%7}, {%0,%1};"
                 : "+r"(d[0]), "+r"(d[1])
                 : "r"(a[0]), "r"(a[1]), "r"(a[2]), "r"(a[3]), "r"(b0), "r"(b1));
}
__device__ __forceinline__ uint32_t smem_u32(const void* p) {
    uint32_t a;
    asm("{ .reg .u64 t; cvta.to.shared.u64 t, %1; cvt.u32.u64 %0, t; }" : "=r"(a) : "l"(p));
    return a;
}
#define CP_ASYNC16(dst, src) \
    asm volatile("cp.async.cg.shared.global [%0], [%1], 16;" :: "r"(dst), "l"(src))
#define CP_COMMIT() asm volatile("cp.async.commit_group;" ::: "memory")
#define CP_WAIT0()  asm volatile("cp.async.wait_group 0;"  ::: "memory")

// ---------------------------------------------------------------- fused prep kernel
#define TH_BLKS (BB*CC/8)    // 192
#define TU_BLKS (BB*QQ/8)    // 192
__global__ __launch_bounds__(256)
void prep_kernel(const float* __restrict__ h, const float* __restrict__ u,
                 const float* __restrict__ w1, const float* __restrict__ b1) {
    const int blk = blockIdx.x;
    const int k = threadIdx.x;

    if (blk >= TH_BLKS + TU_BLKS) {
        const int k0 = (blk - TH_BLKS - TU_BLKS) * 4;
        #pragma unroll
        for (int r = 0; r < 4; r++)
            g_whu_h[(k0 + r) * HH + k] =
                __float2half_rn(w1[(size_t)(k0 + r) * (3 * HH) + 2 * HH + k]);
        return;
    }

    __shared__ float xs[8][HH];
    const bool is_h = blk < TH_BLKS;
    const int r0 = (is_h ? blk : blk - TH_BLKS) * 8;
    const float* x = is_h ? h : u;
    float* outb = is_h ? g_term_h : g_term_u;
    const int coloff = is_h ? 0 : HH;

    #pragma unroll
    for (int r = 0; r < 8; r++) xs[r][k] = x[(size_t)(r0 + r) * HH + k];
    __syncthreads();
    float acc[8];
    const float bv = is_h ? b1[k] : 0.f;
    #pragma unroll
    for (int r = 0; r < 8; r++) acc[r] = bv;
    const float4* wr = reinterpret_cast<const float4*>(w1 + (size_t)k * (3 * HH) + coloff);
    #pragma unroll 8
    for (int i = 0; i < HH / 4; i++) {
        float4 w = wr[i];
        #pragma unroll
        for (int r = 0; r < 8; r++) {
            float4 xv = *reinterpret_cast<const float4*>(&xs[r][4 * i]);
            acc[r] += xv.x * w.x + xv.y * w.y + xv.z * w.z + xv.w * w.w;
        }
    }
    #pragma unroll
    for (int r = 0; r < 8; r++) outb[(size_t)(r0 + r) * KK + k] = acc[r];
}

// ---------------------------------------------------------------- main fp16-acc mma kernel
// Per CTA: (b, c, q-tile 64). CTA tile M=64 x N=256, K chunks of 32.
// 8 warps = 2M x 4N, warp tile 32x64. fp16 accumulation within 2-chunk groups
// (4 chained k16 MMAs), promoted to fp32 every 2 chunks.
#define AS0  0
#define AS1  5120
#define BS0  10240
#define BS1  30720
#define RED  51200
#define HCO  52224
#define THO  53248
#define W2O  54272
#define SMEM_BYTES 55296

__global__ __launch_bounds__(256, 1)
void main_mma_kernel(const float* __restrict__ hmat,
                     const float* __restrict__ u,
                     const float* __restrict__ w2,
                     const float* __restrict__ b2,
                     float* __restrict__ out)
{
    extern __shared__ char sm[];
    __half* As[2] = { reinterpret_cast<__half*>(sm + AS0), reinterpret_cast<__half*>(sm + AS1) };
    __half* Bs[2] = { reinterpret_cast<__half*>(sm + BS0), reinterpret_cast<__half*>(sm + BS1) };
    float* red  = reinterpret_cast<float*>(sm + RED);
    float* h_c  = reinterpret_cast<float*>(sm + HCO);
    float* th_s = reinterpret_cast<float*>(sm + THO);
    float* w2_s = reinterpret_cast<float*>(sm + W2O);

    const int tid = threadIdx.x;
    const int lid = tid & 31;
    const int wid = tid >> 5;
    const int g   = lid >> 2;        // 0..7
    const int t   = lid & 3;         // 0..3
    const int warpM = wid >> 2;      // 0..1  (32 q-rows each)
    const int warpN = wid & 3;       // 0..3  (64 k-cols each)

    const int b  = blockIdx.z;
    const int c  = blockIdx.y;
    const int q0 = blockIdx.x * 64;
    const int bc = b * CC + c;

    h_c[tid]  = hmat[(size_t)bc * HH + tid];
    th_s[tid] = g_term_h[(size_t)bc * KK + tid];
    w2_s[tid] = w2[tid];
    __syncthreads();

    const int arow[2] = { tid >> 3, (tid + 256) >> 3 };
    const int ac4 = tid & 7;
    const float* u_base = u + (size_t)(b * QQ + q0) * HH;
    const int brow[4] = { tid >> 2, (tid + 256) >> 2, (tid + 512) >> 2, (tid + 768) >> 2 };
    const int bseg = tid & 3;

    float acc[2][8][4];          // fp32 master accumulator
    #pragma unroll
    for (int mt = 0; mt < 2; mt++)
        #pragma unroll
        for (int nt = 0; nt < 8; nt++)
            #pragma unroll
            for (int e = 0; e < 4; e++) acc[mt][nt][e] = 0.f;
    uint32_t facc[2][8][2];      // fp16 group accumulator (half2 pairs)

    auto issue_B = [&](int ch, int buf) {
        const uint32_t bdst = smem_u32(Bs[buf]);
        #pragma unroll
        for (int i = 0; i < 4; i++)
            CP_ASYNC16(bdst + brow[i] * (ST * 2) + bseg * 16,
                       g_whu_h + (size_t)brow[i] * HH + ch * 32 + bseg * 8);
        CP_COMMIT();
    };
    auto load_A = [&](int ch, float4* aN) {
        #pragma unroll
        for (int i = 0; i < 2; i++)
            aN[i] = *reinterpret_cast<const float4*>(
                u_base + (size_t)arow[i] * HH + ch * 32 + ac4 * 4);
    };
    auto scale_store_A = [&](int ch, float4* aN, int buf) {
        const int kb = ac4 * 4;
        float4 hv = *reinterpret_cast<const float4*>(&h_c[ch * 32 + kb]);
        #pragma unroll
        for (int i = 0; i < 2; i++) {
            __half2 p0 = __floats2half2_rn(aN[i].x * hv.x, aN[i].y * hv.y);
            __half2 p1 = __floats2half2_rn(aN[i].z * hv.z, aN[i].w * hv.w);
            uint2 pk = { *reinterpret_cast<uint32_t*>(&p0), *reinterpret_cast<uint32_t*>(&p1) };
            *reinterpret_cast<uint2*>(&As[buf][arow[i] * ST + kb]) = pk;
        }
    };

    // prologue
    {
        float4 aN[2];
        load_A(0, aN);
        issue_B(0, 0);
        scale_store_A(0, aN, 0);
        CP_WAIT0();
        __syncthreads();
    }

    for (int ch = 0; ch < 8; ch++) {
        const int buf = ch & 1, nbuf = buf ^ 1;
        float4 aN[2];
        if (ch < 7) {
            issue_B(ch + 1, nbuf);
            load_A(ch + 1, aN);
        }

        if ((ch & 1) == 0) {     // start of 2-chunk group: clear fp16 acc
            #pragma unroll
            for (int mt = 0; mt < 2; mt++)
                #pragma unroll
                for (int nt = 0; nt < 8; nt++) {
                    facc[mt][nt][0] = 0u; facc[mt][nt][1] = 0u;
                }
        }

        const uint32_t* Asu = reinterpret_cast<const uint32_t*>(As[buf]);  // half2 units
        const uint32_t* Bsu = reinterpret_cast<const uint32_t*>(Bs[buf]);
        #pragma unroll
        for (int s = 0; s < 2; s++) {
            const int k2 = s * 8;
            uint32_t af[2][4];
            #pragma unroll
            for (int mt = 0; mt < 2; mt++) {
                const int r0i = (warpM * 32 + mt * 16 + g) * (ST / 2) + k2 + t;
                af[mt][0] = Asu[r0i];
                af[mt][1] = Asu[r0i + 8 * (ST / 2)];
                af[mt][2] = Asu[r0i + 4];
                af[mt][3] = Asu[r0i + 8 * (ST / 2) + 4];
            }
            #pragma unroll
            for (int nt = 0; nt < 8; nt++) {
                const int nb = (warpN * 64 + nt * 8 + g) * (ST / 2) + k2 + t;
                const uint32_t b0 = Bsu[nb];
                const uint32_t b1 = Bsu[nb + 4];
                #pragma unroll
                for (int mt = 0; mt < 2; mt++)
                    mma16h(facc[mt][nt], af[mt], b0, b1);
            }
        }

        if (ch & 1) {            // end of 2-chunk group: promote fp16 -> fp32
            #pragma unroll
            for (int mt = 0; mt < 2; mt++)
                #pragma unroll
                for (int nt = 0; nt < 8; nt++) {
                    float2 lo = __half22float2(*reinterpret_cast<__half2*>(&facc[mt][nt][0]));
                    float2 hi = __half22float2(*reinterpret_cast<__half2*>(&facc[mt][nt][1]));
                    acc[mt][nt][0] += lo.x; acc[mt][nt][1] += lo.y;
                    acc[mt][nt][2] += hi.x; acc[mt][nt][3] += hi.y;
                }
        }

        if (ch < 7) {
            scale_store_A(ch + 1, aN, nbuf);
            CP_WAIT0();
        }
        __syncthreads();
    }

    // ---- epilogue: +term_h +term_u, lrelu, weighted k-reduction ----
    #pragma unroll
    for (int mt = 0; mt < 2; mt++) {
        #pragma unroll
        for (int half = 0; half < 2; half++) {
            const int row = warpM * 32 + mt * 16 + half * 8 + g;
            const int q = q0 + row;
            const float* tu = g_term_u + (size_t)(b * QQ + q) * KK;
            float s = 0.f;
            #pragma unroll
            for (int nt = 0; nt < 8; nt++) {
                const int k = warpN * 64 + nt * 8 + 2 * t;
                float2 tv = *reinterpret_cast<const float2*>(tu + k);
                float v0 = acc[mt][nt][half * 2 + 0] + th_s[k]     + tv.x;
                float v1 = acc[mt][nt][half * 2 + 1] + th_s[k + 1] + tv.y;
                s += w2_s[k]     * lrelu(v0);
                s += w2_s[k + 1] * lrelu(v1);
            }
            s += __shfl_xor_sync(0xffffffffu, s, 1);
            s += __shfl_xor_sync(0xffffffffu, s, 2);
            if (t == 0) red[warpN * 64 + row] = s;
        }
    }
    __syncthreads();
    if (tid < 64) {
        float s = red[tid] + red[64 + tid] + red[128 + tid] + red[192 + tid] + b2[0];
        out[(size_t)bc * QQ + q0 + tid] = lrelu(s);
    }
}

// ---------------------------------------------------------------- launch
extern "C" void kernel_launch(void* const* d_in, const int* in_sizes, int n_in,
                              void* d_out, int out_size) {
    (void)in_sizes; (void)n_in; (void)out_size;
    const float* h_  = (const float*)d_in[0];
    const float* u_  = (const float*)d_in[1];
    const float* w1_ = (const float*)d_in[2];
    const float* b1_ = (const float*)d_in[3];
    const float* w2_ = (const float*)d_in[4];
    const float* b2_ = (const float*)d_in[5];
    float* out_ = (float*)d_out;

    cudaFuncSetAttribute(main_mma_kernel,
                         cudaFuncAttributeMaxDynamicSharedMemorySize, SMEM_BYTES);

    prep_kernel<<<TH_BLKS + TU_BLKS + KK/4, 256>>>(h_, u_, w1_, b1_);

    dim3 grid(QQ / 64, CC, BB);
    main_mma_kernel<<<grid, 256, SMEM_BYTES>>>(h_, u_, w2_, b2_, out_);
}

// round 11
// speedup vs baseline: 1.4077x; 1.4077x over previous
#include <cuda_runtime.h>
#include <cuda_fp16.h>
#include <cstdint>

#define BB 4
#define CC 384
#define QQ 384
#define HH 256
#define KK 256

#define ST 40   // smem row stride in halves (80B): fragment LDS conflict-free

// ---------------------------------------------------------------- scratch
__device__ float g_term_h[BB*CC*KK];                 // term_h + b1 (exact fp32)
__device__ float g_term_u[BB*QQ*KK];                 // term_u     (exact fp32)
__device__ __align__(16) __half g_whu_h[KK*HH];      // W_hu fp16, [k][h] dense

__device__ __forceinline__ float lrelu(float x) {
    return fmaxf(x, 0.f) + 0.01f * fminf(x, 0.f);
}
__device__ __forceinline__ void mma16(float* d, const uint32_t* a, uint32_t b0, uint32_t b1) {
    asm volatile("mma.sync.aligned.m16n8k16.row.col.f32.f16.f16.f32 "
                 "{%0,%1,%2,%3}, {%4,%5,%6,%7}, {%8,%9}, {%0,%1,%2,%3};"
                 : "+f"(d[0]), "+f"(d[1]), "+f"(d[2]), "+f"(d[3])
                 : "r"(a[0]), "r"(a[1]), "r"(a[2]), "r"(a[3]), "r"(b0), "r"(b1));
}
__device__ __forceinline__ uint32_t smem_u32(const void* p) {
    uint32_t a;
    asm("{ .reg .u64 t; cvta.to.shared.u64 t, %1; cvt.u32.u64 %0, t; }" : "=r"(a) : "l"(p));
    return a;
}
#define CP_ASYNC16(dst, src) \
    asm volatile("cp.async.cg.shared.global [%0], [%1], 16;" :: "r"(dst), "l"(src))
#define CP_COMMIT() asm volatile("cp.async.commit_group;" ::: "memory")
#define CP_WAIT0()  asm volatile("cp.async.wait_group 0;"  ::: "memory")

// ---------------------------------------------------------------- fused prep kernel
// One launch, three jobs, 16 rows per term block (halves w1 traffic):
//   blocks [0, 96):    term_h, 16 rows each (with b1)
//   blocks [96, 192):  term_u, 16 rows each (no bias)
//   blocks [192, 256): pack W_hu -> fp16 [k][h], 4 k-rows each
#define TH_BLKS (BB*CC/16)   // 96
#define TU_BLKS (BB*QQ/16)   // 96
__global__ __launch_bounds__(256)
void prep_kernel(const float* __restrict__ h, const float* __restrict__ u,
                 const float* __restrict__ w1, const float* __restrict__ b1) {
    const int blk = blockIdx.x;
    const int k = threadIdx.x;

    if (blk >= TH_BLKS + TU_BLKS) {
        const int k0 = (blk - TH_BLKS - TU_BLKS) * 4;
        #pragma unroll
        for (int r = 0; r < 4; r++)
            g_whu_h[(k0 + r) * HH + k] =
                __float2half_rn(w1[(size_t)(k0 + r) * (3 * HH) + 2 * HH + k]);
        return;
    }

    __shared__ float xs[16][HH];
    const bool is_h = blk < TH_BLKS;
    const int r0 = (is_h ? blk : blk - TH_BLKS) * 16;
    const float* x = is_h ? h : u;
    float* outb = is_h ? g_term_h : g_term_u;
    const int coloff = is_h ? 0 : HH;

    #pragma unroll
    for (int r = 0; r < 16; r++) xs[r][k] = x[(size_t)(r0 + r) * HH + k];
    __syncthreads();
    float acc[16];
    const float bv = is_h ? b1[k] : 0.f;
    #pragma unroll
    for (int r = 0; r < 16; r++) acc[r] = bv;
    const float4* wr = reinterpret_cast<const float4*>(w1 + (size_t)k * (3 * HH) + coloff);
    #pragma unroll 4
    for (int i = 0; i < HH / 4; i++) {
        float4 w = wr[i];
        #pragma unroll
        for (int r = 0; r < 16; r++) {
            float4 xv = *reinterpret_cast<const float4*>(&xs[r][4 * i]);
            acc[r] += xv.x * w.x + xv.y * w.y + xv.z * w.z + xv.w * w.w;
        }
    }
    #pragma unroll
    for (int r = 0; r < 16; r++) outb[(size_t)(r0 + r) * KK + k] = acc[r];
}

// ---------------------------------------------------------------- main fp16 mma kernel
// (R5 configuration — measured at 98.6% of the legacy-HMMA throughput wall.)
// Per CTA: (b, c, q-tile 128). S[q,k] = sum_h (u[b,q,h]*h[b,c,h]) * W_hu[k,h]
// CTA tile M=128 x N=256, K chunks of 32 (m16n8k16), 2-stage cp.async pipe.
// 8 warps = 2M x 4N, warp tile 64x64, per-thread 4x8x4 fp32 acc.
#define AS0  0
#define AS1  10240
#define BS0  20480
#define BS1  40960
#define RED  61440
#define HCO  63488
#define THO  64512
#define W2O  65536
#define SMEM_BYTES 66560

__global__ __launch_bounds__(256, 1)
void main_mma_kernel(const float* __restrict__ hmat,
                     const float* __restrict__ u,
                     const float* __restrict__ w2,
                     const float* __restrict__ b2,
                     float* __restrict__ out)
{
    extern __shared__ char sm[];
    __half* As[2] = { reinterpret_cast<__half*>(sm + AS0), reinterpret_cast<__half*>(sm + AS1) };
    __half* Bs[2] = { reinterpret_cast<__half*>(sm + BS0), reinterpret_cast<__half*>(sm + BS1) };
    float* red  = reinterpret_cast<float*>(sm + RED);
    float* h_c  = reinterpret_cast<float*>(sm + HCO);
    float* th_s = reinterpret_cast<float*>(sm + THO);
    float* w2_s = reinterpret_cast<float*>(sm + W2O);

    const int tid = threadIdx.x;
    const int lid = tid & 31;
    const int wid = tid >> 5;
    const int g   = lid >> 2;
    const int t   = lid & 3;
    const int warpM = wid >> 2;      // 0..1
    const int warpN = wid & 3;       // 0..3

    const int b  = blockIdx.z;
    const int c  = blockIdx.y;
    const int q0 = blockIdx.x * 128;
    const int bc = b * CC + c;

    // prologue keeps only what the mainloop needs (h_c); th_s/w2_s move to epilogue
    h_c[tid] = hmat[(size_t)bc * HH + tid];
    __syncthreads();

    // tile-load coords
    const int arow[4] = { tid >> 3, (tid + 256) >> 3, (tid + 512) >> 3, (tid + 768) >> 3 };
    const int ac4 = tid & 7;
    const float* u_base = u + (size_t)(b * QQ + q0) * HH;
    const int brow[4] = { tid >> 2, (tid + 256) >> 2, (tid + 512) >> 2, (tid + 768) >> 2 };
    const int bseg = tid & 3;

    float acc[4][8][4];
    #pragma unroll
    for (int mt = 0; mt < 4; mt++)
        #pragma unroll
        for (int nt = 0; nt < 8; nt++)
            #pragma unroll
            for (int e = 0; e < 4; e++) acc[mt][nt][e] = 0.f;

    auto issue_B = [&](int ch, int buf) {
        const uint32_t bdst = smem_u32(Bs[buf]);
        #pragma unroll
        for (int i = 0; i < 4; i++)
            CP_ASYNC16(bdst + brow[i] * (ST * 2) + bseg * 16,
                       g_whu_h + (size_t)brow[i] * HH + ch * 32 + bseg * 8);
        CP_COMMIT();
    };
    auto load_A = [&](int ch, float4* aN) {
        #pragma unroll
        for (int i = 0; i < 4; i++)
            aN[i] = *reinterpret_cast<const float4*>(
                u_base + (size_t)arow[i] * HH + ch * 32 + ac4 * 4);
    };
    auto scale_store_A = [&](int ch, float4* aN, int buf) {
        const int kb = ac4 * 4;
        float4 hv = *reinterpret_cast<const float4*>(&h_c[ch * 32 + kb]);
        #pragma unroll
        for (int i = 0; i < 4; i++) {
            __half2 p0 = __floats2half2_rn(aN[i].x * hv.x, aN[i].y * hv.y);
            __half2 p1 = __floats2half2_rn(aN[i].z * hv.z, aN[i].w * hv.w);
            uint2 pk = { *reinterpret_cast<uint32_t*>(&p0), *reinterpret_cast<uint32_t*>(&p1) };
            *reinterpret_cast<uint2*>(&As[buf][arow[i] * ST + kb]) = pk;
        }
    };

    // prologue: stage 0
    {
        float4 aN[4];
        load_A(0, aN);
        issue_B(0, 0);
        scale_store_A(0, aN, 0);
        CP_WAIT0();
        __syncthreads();
    }

    for (int ch = 0; ch < 8; ch++) {
        const int buf = ch & 1, nbuf = buf ^ 1;
        float4 aN[4];
        if (ch < 7) {
            issue_B(ch + 1, nbuf);
            load_A(ch + 1, aN);
        }

        const uint32_t* Asu = reinterpret_cast<const uint32_t*>(As[buf]);  // half2 units
        const uint32_t* Bsu = reinterpret_cast<const uint32_t*>(Bs[buf]);
        #pragma unroll
        for (int s = 0; s < 2; s++) {
            const int k2 = s * 8;
            uint32_t af[4][4];
            #pragma unroll
            for (int mt = 0; mt < 4; mt++) {
                const int r0i = (warpM * 64 + mt * 16 + g) * (ST / 2) + k2 + t;
                af[mt][0] = Asu[r0i];
                af[mt][1] = Asu[r0i + 8 * (ST / 2)];
                af[mt][2] = Asu[r0i + 4];
                af[mt][3] = Asu[r0i + 8 * (ST / 2) + 4];
            }
            #pragma unroll
            for (int nt = 0; nt < 8; nt++) {
                const int nb = (warpN * 64 + nt * 8 + g) * (ST / 2) + k2 + t;
                const uint32_t b0 = Bsu[nb];
                const uint32_t b1 = Bsu[nb + 4];
                #pragma unroll
                for (int mt = 0; mt < 4; mt++)
                    mma16(acc[mt][nt], af[mt], b0, b1);
            }
        }

        if (ch < 7) {
            scale_store_A(ch + 1, aN, nbuf);
            CP_WAIT0();
        }
        __syncthreads();
    }

    // ---- epilogue: load th_s/w2_s here (only place they're used) ----
    th_s[tid] = g_term_h[(size_t)bc * KK + tid];
    w2_s[tid] = w2[tid];
    __syncthreads();

    #pragma unroll
    for (int mt = 0; mt < 4; mt++) {
        #pragma unroll
        for (int half = 0; half < 2; half++) {
            const int row = warpM * 64 + mt * 16 + half * 8 + g;
            const int q = q0 + row;
            const float* tu = g_term_u + (size_t)(b * QQ + q) * KK;
            float s = 0.f;
            #pragma unroll
            for (int nt = 0; nt < 8; nt++) {
                const int k = warpN * 64 + nt * 8 + 2 * t;
                float2 tv = *reinterpret_cast<const float2*>(tu + k);
                float v0 = acc[mt][nt][half * 2 + 0] + th_s[k]     + tv.x;
                float v1 = acc[mt][nt][half * 2 + 1] + th_s[k + 1] + tv.y;
                s += w2_s[k]     * lrelu(v0);
                s += w2_s[k + 1] * lrelu(v1);
            }
            s += __shfl_xor_sync(0xffffffffu, s, 1);
            s += __shfl_xor_sync(0xffffffffu, s, 2);
            if (t == 0) red[warpN * 128 + row] = s;
        }
    }
    __syncthreads();
    if (tid < 128) {
        float s = red[tid] + red[128 + tid] + red[256 + tid] + red[384 + tid] + b2[0];
        out[(size_t)bc * QQ + q0 + tid] = lrelu(s);
    }
}

// ---------------------------------------------------------------- launch
extern "C" void kernel_launch(void* const* d_in, const int* in_sizes, int n_in,
                              void* d_out, int out_size) {
    (void)in_sizes; (void)n_in; (void)out_size;
    const float* h_  = (const float*)d_in[0];
    const float* u_  = (const float*)d_in[1];
    const float* w1_ = (const float*)d_in[2];
    const float* b1_ = (const float*)d_in[3];
    const float* w2_ = (const float*)d_in[4];
    const float* b2_ = (const float*)d_in[5];
    float* out_ = (float*)d_out;

    cudaFuncSetAttribute(main_mma_kernel,
                         cudaFuncAttributeMaxDynamicSharedMemorySize, SMEM_BYTES);

    prep_kernel<<<TH_BLKS + TU_BLKS + KK/4, 256>>>(h_, u_, w1_, b1_);

    dim3 grid(QQ / 128, CC, BB);
    main_mma_kernel<<<grid, 256, SMEM_BYTES>>>(h_, u_, w2_, b2_, out_);
}

// round 12
// speedup vs baseline: 1.5369x; 1.0918x over previous
#include <cuda_runtime.h>
#include <cuda_fp16.h>
#include <cstdint>

#define BB 4
#define CC 384
#define QQ 384
#define HH 256
#define KK 256

#define ST 40   // smem row stride in halves (80B): fragment LDS conflict-free

// ---------------------------------------------------------------- scratch
__device__ float g_term_h[BB*CC*KK];                 // term_h + b1 (exact fp32)
__device__ float g_term_u[BB*QQ*KK];                 // term_u     (exact fp32)
__device__ __align__(16) __half g_whu_h[KK*HH];      // W_hu fp16, [k][h] dense

__device__ __forceinline__ float lrelu(float x) {
    return fmaxf(x, 0.f) + 0.01f * fminf(x, 0.f);
}
__device__ __forceinline__ void mma16(float* d, const uint32_t* a, uint32_t b0, uint32_t b1) {
    asm volatile("mma.sync.aligned.m16n8k16.row.col.f32.f16.f16.f32 "
                 "{%0,%1,%2,%3}, {%4,%5,%6,%7}, {%8,%9}, {%0,%1,%2,%3};"
                 : "+f"(d[0]), "+f"(d[1]), "+f"(d[2]), "+f"(d[3])
                 : "r"(a[0]), "r"(a[1]), "r"(a[2]), "r"(a[3]), "r"(b0), "r"(b1));
}
__device__ __forceinline__ uint32_t smem_u32(const void* p) {
    uint32_t a;
    asm("{ .reg .u64 t; cvta.to.shared.u64 t, %1; cvt.u32.u64 %0, t; }" : "=r"(a) : "l"(p));
    return a;
}
#define CP_ASYNC16(dst, src) \
    asm volatile("cp.async.cg.shared.global [%0], [%1], 16;" :: "r"(dst), "l"(src))
#define CP_COMMIT() asm volatile("cp.async.commit_group;" ::: "memory")
#define CP_WAIT0()  asm volatile("cp.async.wait_group 0;"  ::: "memory")

// ---------------------------------------------------------------- fused prep kernel
// One launch, three jobs, 16 rows per term block (measured best):
//   blocks [0, 96):    term_h, 16 rows each (with b1)
//   blocks [96, 192):  term_u, 16 rows each (no bias)
//   blocks [192, 256): pack W_hu -> fp16 [k][h], 4 k-rows each
#define TH_BLKS (BB*CC/16)   // 96
#define TU_BLKS (BB*QQ/16)   // 96
__global__ __launch_bounds__(256)
void prep_kernel(const float* __restrict__ h, const float* __restrict__ u,
                 const float* __restrict__ w1, const float* __restrict__ b1) {
    const int blk = blockIdx.x;
    const int k = threadIdx.x;

    if (blk >= TH_BLKS + TU_BLKS) {
        const int k0 = (blk - TH_BLKS - TU_BLKS) * 4;
        #pragma unroll
        for (int r = 0; r < 4; r++)
            g_whu_h[(k0 + r) * HH + k] =
                __float2half_rn(w1[(size_t)(k0 + r) * (3 * HH) + 2 * HH + k]);
        return;
    }

    __shared__ float xs[16][HH];
    const bool is_h = blk < TH_BLKS;
    const int r0 = (is_h ? blk : blk - TH_BLKS) * 16;
    const float* x = is_h ? h : u;
    float* outb = is_h ? g_term_h : g_term_u;
    const int coloff = is_h ? 0 : HH;

    #pragma unroll
    for (int r = 0; r < 16; r++) xs[r][k] = x[(size_t)(r0 + r) * HH + k];
    __syncthreads();
    float acc[16];
    const float bv = is_h ? b1[k] : 0.f;
    #pragma unroll
    for (int r = 0; r < 16; r++) acc[r] = bv;
    const float4* wr = reinterpret_cast<const float4*>(w1 + (size_t)k * (3 * HH) + coloff);
    #pragma unroll 4
    for (int i = 0; i < HH / 4; i++) {
        float4 w = wr[i];
        #pragma unroll
        for (int r = 0; r < 16; r++) {
            float4 xv = *reinterpret_cast<const float4*>(&xs[r][4 * i]);
            acc[r] += xv.x * w.x + xv.y * w.y + xv.z * w.z + xv.w * w.w;
        }
    }
    #pragma unroll
    for (int r = 0; r < 16; r++) outb[(size_t)(r0 + r) * KK + k] = acc[r];
}

// ---------------------------------------------------------------- main fp16 mma kernel
// (R9/R5 configuration, measured 432.4us — 98.6% of the legacy-HMMA wall.)
// Per CTA: (b, c, q-tile 128). S[q,k] = sum_h (u[b,q,h]*h[b,c,h]) * W_hu[k,h]
// CTA tile M=128 x N=256, K chunks of 32 (m16n8k16), 2-stage cp.async pipe.
// 8 warps = 2M x 4N, warp tile 64x64, per-thread 4x8x4 fp32 acc.
// th_s/w2_s loaded in the PROLOGUE (latency hides behind first tile load).
#define AS0  0
#define AS1  10240
#define BS0  20480
#define BS1  40960
#define RED  61440
#define HCO  63488
#define THO  64512
#define W2O  65536
#define SMEM_BYTES 66560

__global__ __launch_bounds__(256, 1)
void main_mma_kernel(const float* __restrict__ hmat,
                     const float* __restrict__ u,
                     const float* __restrict__ w2,
                     const float* __restrict__ b2,
                     float* __restrict__ out)
{
    extern __shared__ char sm[];
    __half* As[2] = { reinterpret_cast<__half*>(sm + AS0), reinterpret_cast<__half*>(sm + AS1) };
    __half* Bs[2] = { reinterpret_cast<__half*>(sm + BS0), reinterpret_cast<__half*>(sm + BS1) };
    float* red  = reinterpret_cast<float*>(sm + RED);
    float* h_c  = reinterpret_cast<float*>(sm + HCO);
    float* th_s = reinterpret_cast<float*>(sm + THO);
    float* w2_s = reinterpret_cast<float*>(sm + W2O);

    const int tid = threadIdx.x;
    const int lid = tid & 31;
    const int wid = tid >> 5;
    const int g   = lid >> 2;
    const int t   = lid & 3;
    const int warpM = wid >> 2;      // 0..1
    const int warpN = wid & 3;       // 0..3

    const int b  = blockIdx.z;
    const int c  = blockIdx.y;
    const int q0 = blockIdx.x * 128;
    const int bc = b * CC + c;

    h_c[tid]  = hmat[(size_t)bc * HH + tid];
    th_s[tid] = g_term_h[(size_t)bc * KK + tid];
    w2_s[tid] = w2[tid];
    __syncthreads();

    // tile-load coords
    const int arow[4] = { tid >> 3, (tid + 256) >> 3, (tid + 512) >> 3, (tid + 768) >> 3 };
    const int ac4 = tid & 7;
    const float* u_base = u + (size_t)(b * QQ + q0) * HH;
    const int brow[4] = { tid >> 2, (tid + 256) >> 2, (tid + 512) >> 2, (tid + 768) >> 2 };
    const int bseg = tid & 3;

    float acc[4][8][4];
    #pragma unroll
    for (int mt = 0; mt < 4; mt++)
        #pragma unroll
        for (int nt = 0; nt < 8; nt++)
            #pragma unroll
            for (int e = 0; e < 4; e++) acc[mt][nt][e] = 0.f;

    auto issue_B = [&](int ch, int buf) {
        const uint32_t bdst = smem_u32(Bs[buf]);
        #pragma unroll
        for (int i = 0; i < 4; i++)
            CP_ASYNC16(bdst + brow[i] * (ST * 2) + bseg * 16,
                       g_whu_h + (size_t)brow[i] * HH + ch * 32 + bseg * 8);
        CP_COMMIT();
    };
    auto load_A = [&](int ch, float4* aN) {
        #pragma unroll
        for (int i = 0; i < 4; i++)
            aN[i] = *reinterpret_cast<const float4*>(
                u_base + (size_t)arow[i] * HH + ch * 32 + ac4 * 4);
    };
    auto scale_store_A = [&](int ch, float4* aN, int buf) {
        const int kb = ac4 * 4;
        float4 hv = *reinterpret_cast<const float4*>(&h_c[ch * 32 + kb]);
        #pragma unroll
        for (int i = 0; i < 4; i++) {
            __half2 p0 = __floats2half2_rn(aN[i].x * hv.x, aN[i].y * hv.y);
            __half2 p1 = __floats2half2_rn(aN[i].z * hv.z, aN[i].w * hv.w);
            uint2 pk = { *reinterpret_cast<uint32_t*>(&p0), *reinterpret_cast<uint32_t*>(&p1) };
            *reinterpret_cast<uint2*>(&As[buf][arow[i] * ST + kb]) = pk;
        }
    };

    // prologue: stage 0
    {
        float4 aN[4];
        load_A(0, aN);
        issue_B(0, 0);
        scale_store_A(0, aN, 0);
        CP_WAIT0();
        __syncthreads();
    }

    for (int ch = 0; ch < 8; ch++) {
        const int buf = ch & 1, nbuf = buf ^ 1;
        float4 aN[4];
        if (ch < 7) {
            issue_B(ch + 1, nbuf);
            load_A(ch + 1, aN);
        }

        const uint32_t* Asu = reinterpret_cast<const uint32_t*>(As[buf]);  // half2 units
        const uint32_t* Bsu = reinterpret_cast<const uint32_t*>(Bs[buf]);
        #pragma unroll
        for (int s = 0; s < 2; s++) {
            const int k2 = s * 8;
            uint32_t af[4][4];
            #pragma unroll
            for (int mt = 0; mt < 4; mt++) {
                const int r0i = (warpM * 64 + mt * 16 + g) * (ST / 2) + k2 + t;
                af[mt][0] = Asu[r0i];
                af[mt][1] = Asu[r0i + 8 * (ST / 2)];
                af[mt][2] = Asu[r0i + 4];
                af[mt][3] = Asu[r0i + 8 * (ST / 2) + 4];
            }
            #pragma unroll
            for (int nt = 0; nt < 8; nt++) {
                const int nb = (warpN * 64 + nt * 8 + g) * (ST / 2) + k2 + t;
                const uint32_t b0 = Bsu[nb];
                const uint32_t b1 = Bsu[nb + 4];
                #pragma unroll
                for (int mt = 0; mt < 4; mt++)
                    mma16(acc[mt][nt], af[mt], b0, b1);
            }
        }

        if (ch < 7) {
            scale_store_A(ch + 1, aN, nbuf);
            CP_WAIT0();
        }
        __syncthreads();
    }

    // ---- epilogue: +term_h +term_u, lrelu, weighted k-reduction ----
    #pragma unroll
    for (int mt = 0; mt < 4; mt++) {
        #pragma unroll
        for (int half = 0; half < 2; half++) {
            const int row = warpM * 64 + mt * 16 + half * 8 + g;
            const int q = q0 + row;
            const float* tu = g_term_u + (size_t)(b * QQ + q) * KK;
            float s = 0.f;
            #pragma unroll
            for (int nt = 0; nt < 8; nt++) {
                const int k = warpN * 64 + nt * 8 + 2 * t;
                float2 tv = *reinterpret_cast<const float2*>(tu + k);
                float v0 = acc[mt][nt][half * 2 + 0] + th_s[k]     + tv.x;
                float v1 = acc[mt][nt][half * 2 + 1] + th_s[k + 1] + tv.y;
                s += w2_s[k]     * lrelu(v0);
                s += w2_s[k + 1] * lrelu(v1);
            }
            s += __shfl_xor_sync(0xffffffffu, s, 1);
            s += __shfl_xor_sync(0xffffffffu, s, 2);
            if (t == 0) red[warpN * 128 + row] = s;
        }
    }
    __syncthreads();
    if (tid < 128) {
        float s = red[tid] + red[128 + tid] + red[256 + tid] + red[384 + tid] + b2[0];
        out[(size_t)bc * QQ + q0 + tid] = lrelu(s);
    }
}

// ---------------------------------------------------------------- launch
extern "C" void kernel_launch(void* const* d_in, const int* in_sizes, int n_in,
                              void* d_out, int out_size) {
    (void)in_sizes; (void)n_in; (void)out_size;
    const float* h_  = (const float*)d_in[0];
    const float* u_  = (const float*)d_in[1];
    const float* w1_ = (const float*)d_in[2];
    const float* b1_ = (const float*)d_in[3];
    const float* w2_ = (const float*)d_in[4];
    const float* b2_ = (const float*)d_in[5];
    float* out_ = (float*)d_out;

    cudaFuncSetAttribute(main_mma_kernel,
                         cudaFuncAttributeMaxDynamicSharedMemorySize, SMEM_BYTES);

    prep_kernel<<<TH_BLKS + TU_BLKS + KK/4, 256>>>(h_, u_, w1_, b1_);

    dim3 grid(QQ / 128, CC, BB);
    main_mma_kernel<<<grid, 256, SMEM_BYTES>>>(h_, u_, w2_, b2_, out_);
}

// round 13
// speedup vs baseline: 1.6005x; 1.0414x over previous
#include <cuda_runtime.h>
#include <cuda_fp16.h>
#include <cstdint>

#define BB 4
#define CC 384
#define QQ 384
#define HH 256
#define KK 256

#define ST 40   // smem row stride in halves (80B): fragment LDS conflict-free

// ---------------------------------------------------------------- scratch
__device__ float g_term_h[BB*CC*KK];                 // term_h + b1
__device__ float g_term_u[BB*QQ*KK];                 // term_u
__device__ __align__(16) __half g_whu_h[KK*HH];      // W_hu fp16, [k][h] dense

__device__ __forceinline__ float lrelu(float x) {
    return fmaxf(x, 0.f) + 0.01f * fminf(x, 0.f);
}
__device__ __forceinline__ void mma16(float* d, const uint32_t* a, uint32_t b0, uint32_t b1) {
    asm volatile("mma.sync.aligned.m16n8k16.row.col.f32.f16.f16.f32 "
                 "{%0,%1,%2,%3}, {%4,%5,%6,%7}, {%8,%9}, {%0,%1,%2,%3};"
                 : "+f"(d[0]), "+f"(d[1]), "+f"(d[2]), "+f"(d[3])
                 : "r"(a[0]), "r"(a[1]), "r"(a[2]), "r"(a[3]), "r"(b0), "r"(b1));
}
__device__ __forceinline__ uint32_t smem_u32(const void* p) {
    uint32_t a;
    asm("{ .reg .u64 t; cvta.to.shared.u64 t, %1; cvt.u32.u64 %0, t; }" : "=r"(a) : "l"(p));
    return a;
}
#define CP_ASYNC16(dst, src) \
    asm volatile("cp.async.cg.shared.global [%0], [%1], 16;" :: "r"(dst), "l"(src))
#define CP_COMMIT() asm volatile("cp.async.commit_group;" ::: "memory")
#define CP_WAIT0()  asm volatile("cp.async.wait_group 0;"  ::: "memory")

__device__ __forceinline__ uint2 pack_h4(float4 v) {
    __half2 p0 = __floats2half2_rn(v.x, v.y);
    __half2 p1 = __floats2half2_rn(v.z, v.w);
    return make_uint2(*reinterpret_cast<uint32_t*>(&p0), *reinterpret_cast<uint32_t*>(&p1));
}

// ---------------------------------------------------------------- tensor-core prep kernel
// One launch, one wave (112 blocks):
//   blocks [0, 24):   term_h tiles, M=64 rows of h each, +b1     (fp16 MMA, fp32 acc)
//   blocks [24, 48):  term_u tiles, M=64 rows of u each
//   blocks [48, 112): pack W_hu -> fp16 [k][h], 4 k-rows each
__global__ __launch_bounds__(256)
void prep_mma_kernel(const float* __restrict__ h, const float* __restrict__ u,
                     const float* __restrict__ w1, const float* __restrict__ b1) {
    const int blk = blockIdx.x;
    const int tid = threadIdx.x;

    if (blk >= 48) {   // ---- pack W_hu ----
        const int k0 = (blk - 48) * 4;
        #pragma unroll
        for (int r = 0; r < 4; r++)
            g_whu_h[(k0 + r) * HH + tid] =
                __float2half_rn(w1[(size_t)(k0 + r) * (3 * HH) + 2 * HH + tid]);
        return;
    }

    // ---- term GEMM tile: out[r0..r0+64) x [0,256) = x @ W^T (+b1 for h-job) ----
    __shared__ __half As_[64 * ST];
    __shared__ __half Bs_[256 * ST];

    const bool is_h = blk < 24;
    const int r0 = (is_h ? blk : blk - 24) * 64;
    const float* x = is_h ? h : u;
    float* outb = is_h ? g_term_h : g_term_u;
    const int coloff = is_h ? 0 : HH;

    const int lid = tid & 31;
    const int wid = tid >> 5;
    const int g   = lid >> 2;
    const int t   = lid & 3;
    const int warpM = wid >> 2;      // 0..1 (32 rows each)
    const int warpN = wid & 3;       // 0..3 (64 k-cols each)

    float acc[2][8][4];
    #pragma unroll
    for (int mt = 0; mt < 2; mt++)
        #pragma unroll
        for (int nt = 0; nt < 8; nt++)
            #pragma unroll
            for (int e = 0; e < 4; e++) acc[mt][nt][e] = 0.f;

    for (int ch = 0; ch < 8; ch++) {
        // A tile: 64 x 32 fp32 -> fp16 (512 float4 segs over 2 iters)
        #pragma unroll
        for (int i = 0; i < 2; i++) {
            const int idx = tid + i * 256;
            const int row = idx >> 3, c4 = idx & 7;
            float4 v = *reinterpret_cast<const float4*>(
                x + (size_t)(r0 + row) * HH + ch * 32 + c4 * 4);
            *reinterpret_cast<uint2*>(&As_[row * ST + c4 * 4]) = pack_h4(v);
        }
        // B tile: 256 x 32 fp32 (w1 section) -> fp16 (2048 segs over 8 iters)
        #pragma unroll
        for (int i = 0; i < 8; i++) {
            const int idx = tid + i * 256;
            const int row = idx >> 3, c4 = idx & 7;
            float4 v = *reinterpret_cast<const float4*>(
                w1 + (size_t)row * (3 * HH) + coloff + ch * 32 + c4 * 4);
            *reinterpret_cast<uint2*>(&Bs_[row * ST + c4 * 4]) = pack_h4(v);
        }
        __syncthreads();

        const uint32_t* Asu = reinterpret_cast<const uint32_t*>(As_);
        const uint32_t* Bsu = reinterpret_cast<const uint32_t*>(Bs_);
        #pragma unroll
        for (int s = 0; s < 2; s++) {
            const int k2 = s * 8;
            uint32_t af[2][4];
            #pragma unroll
            for (int mt = 0; mt < 2; mt++) {
                const int r0i = (warpM * 32 + mt * 16 + g) * (ST / 2) + k2 + t;
                af[mt][0] = Asu[r0i];
                af[mt][1] = Asu[r0i + 8 * (ST / 2)];
                af[mt][2] = Asu[r0i + 4];
                af[mt][3] = Asu[r0i + 8 * (ST / 2) + 4];
            }
            #pragma unroll
            for (int nt = 0; nt < 8; nt++) {
                const int nb = (warpN * 64 + nt * 8 + g) * (ST / 2) + k2 + t;
                const uint32_t b0 = Bsu[nb];
                const uint32_t b1r = Bsu[nb + 4];
                #pragma unroll
                for (int mt = 0; mt < 2; mt++)
                    mma16(acc[mt][nt], af[mt], b0, b1r);
            }
        }
        __syncthreads();
    }

    // write out (+b1 for term_h)
    #pragma unroll
    for (int nt = 0; nt < 8; nt++) {
        const int k = warpN * 64 + nt * 8 + 2 * t;
        float2 bv = is_h ? *reinterpret_cast<const float2*>(b1 + k)
                         : make_float2(0.f, 0.f);
        #pragma unroll
        for (int mt = 0; mt < 2; mt++)
            #pragma unroll
            for (int half = 0; half < 2; half++) {
                const int row = warpM * 32 + mt * 16 + half * 8 + g;
                float2 v = make_float2(acc[mt][nt][half * 2 + 0] + bv.x,
                                       acc[mt][nt][half * 2 + 1] + bv.y);
                *reinterpret_cast<float2*>(outb + (size_t)(r0 + row) * KK + k) = v;
            }
    }
}

// ---------------------------------------------------------------- main fp16 mma kernel
// (R12 configuration — measured 431.8us, 98.6% of the legacy-HMMA wall. UNCHANGED.)
#define AS0  0
#define AS1  10240
#define BS0  20480
#define BS1  40960
#define RED  61440
#define HCO  63488
#define THO  64512
#define W2O  65536
#define SMEM_BYTES 66560

__global__ __launch_bounds__(256, 1)
void main_mma_kernel(const float* __restrict__ hmat,
                     const float* __restrict__ u,
                     const float* __restrict__ w2,
                     const float* __restrict__ b2,
                     float* __restrict__ out)
{
    extern __shared__ char sm[];
    __half* As[2] = { reinterpret_cast<__half*>(sm + AS0), reinterpret_cast<__half*>(sm + AS1) };
    __half* Bs[2] = { reinterpret_cast<__half*>(sm + BS0), reinterpret_cast<__half*>(sm + BS1) };
    float* red  = reinterpret_cast<float*>(sm + RED);
    float* h_c  = reinterpret_cast<float*>(sm + HCO);
    float* th_s = reinterpret_cast<float*>(sm + THO);
    float* w2_s = reinterpret_cast<float*>(sm + W2O);

    const int tid = threadIdx.x;
    const int lid = tid & 31;
    const int wid = tid >> 5;
    const int g   = lid >> 2;
    const int t   = lid & 3;
    const int warpM = wid >> 2;      // 0..1
    const int warpN = wid & 3;       // 0..3

    const int b  = blockIdx.z;
    const int c  = blockIdx.y;
    const int q0 = blockIdx.x * 128;
    const int bc = b * CC + c;

    h_c[tid]  = hmat[(size_t)bc * HH + tid];
    th_s[tid] = g_term_h[(size_t)bc * KK + tid];
    w2_s[tid] = w2[tid];
    __syncthreads();

    const int arow[4] = { tid >> 3, (tid + 256) >> 3, (tid + 512) >> 3, (tid + 768) >> 3 };
    const int ac4 = tid & 7;
    const float* u_base = u + (size_t)(b * QQ + q0) * HH;
    const int brow[4] = { tid >> 2, (tid + 256) >> 2, (tid + 512) >> 2, (tid + 768) >> 2 };
    const int bseg = tid & 3;

    float acc[4][8][4];
    #pragma unroll
    for (int mt = 0; mt < 4; mt++)
        #pragma unroll
        for (int nt = 0; nt < 8; nt++)
            #pragma unroll
            for (int e = 0; e < 4; e++) acc[mt][nt][e] = 0.f;

    auto issue_B = [&](int ch, int buf) {
        const uint32_t bdst = smem_u32(Bs[buf]);
        #pragma unroll
        for (int i = 0; i < 4; i++)
            CP_ASYNC16(bdst + brow[i] * (ST * 2) + bseg * 16,
                       g_whu_h + (size_t)brow[i] * HH + ch * 32 + bseg * 8);
        CP_COMMIT();
    };
    auto load_A = [&](int ch, float4* aN) {
        #pragma unroll
        for (int i = 0; i < 4; i++)
            aN[i] = *reinterpret_cast<const float4*>(
                u_base + (size_t)arow[i] * HH + ch * 32 + ac4 * 4);
    };
    auto scale_store_A = [&](int ch, float4* aN, int buf) {
        const int kb = ac4 * 4;
        float4 hv = *reinterpret_cast<const float4*>(&h_c[ch * 32 + kb]);
        #pragma unroll
        for (int i = 0; i < 4; i++) {
            float4 v = make_float4(aN[i].x * hv.x, aN[i].y * hv.y,
                                   aN[i].z * hv.z, aN[i].w * hv.w);
            *reinterpret_cast<uint2*>(&As[buf][arow[i] * ST + kb]) = pack_h4(v);
        }
    };

    // prologue: stage 0
    {
        float4 aN[4];
        load_A(0, aN);
        issue_B(0, 0);
        scale_store_A(0, aN, 0);
        CP_WAIT0();
        __syncthreads();
    }

    for (int ch = 0; ch < 8; ch++) {
        const int buf = ch & 1, nbuf = buf ^ 1;
        float4 aN[4];
        if (ch < 7) {
            issue_B(ch + 1, nbuf);
            load_A(ch + 1, aN);
        }

        const uint32_t* Asu = reinterpret_cast<const uint32_t*>(As[buf]);  // half2 units
        const uint32_t* Bsu = reinterpret_cast<const uint32_t*>(Bs[buf]);
        #pragma unroll
        for (int s = 0; s < 2; s++) {
            const int k2 = s * 8;
            uint32_t af[4][4];
            #pragma unroll
            for (int mt = 0; mt < 4; mt++) {
                const int r0i = (warpM * 64 + mt * 16 + g) * (ST / 2) + k2 + t;
                af[mt][0] = Asu[r0i];
                af[mt][1] = Asu[r0i + 8 * (ST / 2)];
                af[mt][2] = Asu[r0i + 4];
                af[mt][3] = Asu[r0i + 8 * (ST / 2) + 4];
            }
            #pragma unroll
            for (int nt = 0; nt < 8; nt++) {
                const int nb = (warpN * 64 + nt * 8 + g) * (ST / 2) + k2 + t;
                const uint32_t b0 = Bsu[nb];
                const uint32_t b1 = Bsu[nb + 4];
                #pragma unroll
                for (int mt = 0; mt < 4; mt++)
                    mma16(acc[mt][nt], af[mt], b0, b1);
            }
        }

        if (ch < 7) {
            scale_store_A(ch + 1, aN, nbuf);
            CP_WAIT0();
        }
        __syncthreads();
    }

    // ---- epilogue: +term_h +term_u, lrelu, weighted k-reduction ----
    #pragma unroll
    for (int mt = 0; mt < 4; mt++) {
        #pragma unroll
        for (int half = 0; half < 2; half++) {
            const int row = warpM * 64 + mt * 16 + half * 8 + g;
            const int q = q0 + row;
            const float* tu = g_term_u + (size_t)(b * QQ + q) * KK;
            float s = 0.f;
            #pragma unroll
            for (int nt = 0; nt < 8; nt++) {
                const int k = warpN * 64 + nt * 8 + 2 * t;
                float2 tv = *reinterpret_cast<const float2*>(tu + k);
                float v0 = acc[mt][nt][half * 2 + 0] + th_s[k]     + tv.x;
                float v1 = acc[mt][nt][half * 2 + 1] + th_s[k + 1] + tv.y;
                s += w2_s[k]     * lrelu(v0);
                s += w2_s[k + 1] * lrelu(v1);
            }
            s += __shfl_xor_sync(0xffffffffu, s, 1);
            s += __shfl_xor_sync(0xffffffffu, s, 2);
            if (t == 0) red[warpN * 128 + row] = s;
        }
    }
    __syncthreads();
    if (tid < 128) {
        float s = red[tid] + red[128 + tid] + red[256 + tid] + red[384 + tid] + b2[0];
        out[(size_t)bc * QQ + q0 + tid] = lrelu(s);
    }
}

// ---------------------------------------------------------------- launch
extern "C" void kernel_launch(void* const* d_in, const int* in_sizes, int n_in,
                              void* d_out, int out_size) {
    (void)in_sizes; (void)n_in; (void)out_size;
    const float* h_  = (const float*)d_in[0];
    const float* u_  = (const float*)d_in[1];
    const float* w1_ = (const float*)d_in[2];
    const float* b1_ = (const float*)d_in[3];
    const float* w2_ = (const float*)d_in[4];
    const float* b2_ = (const float*)d_in[5];
    float* out_ = (float*)d_out;

    cudaFuncSetAttribute(main_mma_kernel,
                         cudaFuncAttributeMaxDynamicSharedMemorySize, SMEM_BYTES);

    prep_mma_kernel<<<112, 256>>>(h_, u_, w1_, b1_);

    dim3 grid(QQ / 128, CC, BB);
    main_mma_kernel<<<grid, 256, SMEM_BYTES>>>(h_, u_, w2_, b2_, out_);
}

// round 14
// speedup vs baseline: 1.7528x; 1.0952x over previous
#include <cuda_runtime.h>
#include <cuda_fp16.h>
#include <cstdint>

#define BB 4
#define CC 384
#define QQ 384
#define HH 256
#define KK 256

#define ST 40                 // smem row stride in halves (80B)
#define NTILES (BB*CC*3)      // 4608 q-tiles of 128

// ---------------------------------------------------------------- scratch
__device__ float g_term_h[BB*CC*KK];                 // term_h + b1
__device__ float g_term_u[BB*QQ*KK];                 // term_u
__device__ __align__(16) __half g_whu_h[KK*HH];      // W_hu fp16, [k][h] dense

__device__ __forceinline__ float lrelu(float x) {
    return fmaxf(x, 0.f) + 0.01f * fminf(x, 0.f);
}
__device__ __forceinline__ void mma16(float* d, const uint32_t* a, uint32_t b0, uint32_t b1) {
    asm volatile("mma.sync.aligned.m16n8k16.row.col.f32.f16.f16.f32 "
                 "{%0,%1,%2,%3}, {%4,%5,%6,%7}, {%8,%9}, {%0,%1,%2,%3};"
                 : "+f"(d[0]), "+f"(d[1]), "+f"(d[2]), "+f"(d[3])
                 : "r"(a[0]), "r"(a[1]), "r"(a[2]), "r"(a[3]), "r"(b0), "r"(b1));
}
__device__ __forceinline__ uint32_t smem_u32(const void* p) {
    uint32_t a;
    asm("{ .reg .u64 t; cvta.to.shared.u64 t, %1; cvt.u32.u64 %0, t; }" : "=r"(a) : "l"(p));
    return a;
}
#define CP_ASYNC16(dst, src) \
    asm volatile("cp.async.cg.shared.global [%0], [%1], 16;" :: "r"(dst), "l"(src))
#define CP_COMMIT() asm volatile("cp.async.commit_group;" ::: "memory")
#define CP_WAIT0()  asm volatile("cp.async.wait_group 0;"  ::: "memory")

__device__ __forceinline__ uint2 pack_h4(float4 v) {
    __half2 p0 = __floats2half2_rn(v.x, v.y);
    __half2 p1 = __floats2half2_rn(v.z, v.w);
    return make_uint2(*reinterpret_cast<uint32_t*>(&p0), *reinterpret_cast<uint32_t*>(&p1));
}

// ---------------------------------------------------------------- tensor-core prep kernel
// (R13 configuration — measured ~7.3us. UNCHANGED.)
__global__ __launch_bounds__(256)
void prep_mma_kernel(const float* __restrict__ h, const float* __restrict__ u,
                     const float* __restrict__ w1, const float* __restrict__ b1) {
    const int blk = blockIdx.x;
    const int tid = threadIdx.x;

    if (blk >= 48) {   // ---- pack W_hu ----
        const int k0 = (blk - 48) * 4;
        #pragma unroll
        for (int r = 0; r < 4; r++)
            g_whu_h[(k0 + r) * HH + tid] =
                __float2half_rn(w1[(size_t)(k0 + r) * (3 * HH) + 2 * HH + tid]);
        return;
    }

    __shared__ __half As_[64 * ST];
    __shared__ __half Bs_[256 * ST];

    const bool is_h = blk < 24;
    const int r0 = (is_h ? blk : blk - 24) * 64;
    const float* x = is_h ? h : u;
    float* outb = is_h ? g_term_h : g_term_u;
    const int coloff = is_h ? 0 : HH;

    const int lid = tid & 31;
    const int wid = tid >> 5;
    const int g   = lid >> 2;
    const int t   = lid & 3;
    const int warpM = wid >> 2;
    const int warpN = wid & 3;

    float acc[2][8][4];
    #pragma unroll
    for (int mt = 0; mt < 2; mt++)
        #pragma unroll
        for (int nt = 0; nt < 8; nt++)
            #pragma unroll
            for (int e = 0; e < 4; e++) acc[mt][nt][e] = 0.f;

    for (int ch = 0; ch < 8; ch++) {
        #pragma unroll
        for (int i = 0; i < 2; i++) {
            const int idx = tid + i * 256;
            const int row = idx >> 3, c4 = idx & 7;
            float4 v = *reinterpret_cast<const float4*>(
                x + (size_t)(r0 + row) * HH + ch * 32 + c4 * 4);
            *reinterpret_cast<uint2*>(&As_[row * ST + c4 * 4]) = pack_h4(v);
        }
        #pragma unroll
        for (int i = 0; i < 8; i++) {
            const int idx = tid + i * 256;
            const int row = idx >> 3, c4 = idx & 7;
            float4 v = *reinterpret_cast<const float4*>(
                w1 + (size_t)row * (3 * HH) + coloff + ch * 32 + c4 * 4);
            *reinterpret_cast<uint2*>(&Bs_[row * ST + c4 * 4]) = pack_h4(v);
        }
        __syncthreads();

        const uint32_t* Asu = reinterpret_cast<const uint32_t*>(As_);
        const uint32_t* Bsu = reinterpret_cast<const uint32_t*>(Bs_);
        #pragma unroll
        for (int s = 0; s < 2; s++) {
            const int k2 = s * 8;
            uint32_t af[2][4];
            #pragma unroll
            for (int mt = 0; mt < 2; mt++) {
                const int r0i = (warpM * 32 + mt * 16 + g) * (ST / 2) + k2 + t;
                af[mt][0] = Asu[r0i];
                af[mt][1] = Asu[r0i + 8 * (ST / 2)];
                af[mt][2] = Asu[r0i + 4];
                af[mt][3] = Asu[r0i + 8 * (ST / 2) + 4];
            }
            #pragma unroll
            for (int nt = 0; nt < 8; nt++) {
                const int nb = (warpN * 64 + nt * 8 + g) * (ST / 2) + k2 + t;
                const uint32_t b0 = Bsu[nb];
                const uint32_t b1r = Bsu[nb + 4];
                #pragma unroll
                for (int mt = 0; mt < 2; mt++)
                    mma16(acc[mt][nt], af[mt], b0, b1r);
            }
        }
        __syncthreads();
    }

    #pragma unroll
    for (int nt = 0; nt < 8; nt++) {
        const int k = warpN * 64 + nt * 8 + 2 * t;
        float2 bv = is_h ? *reinterpret_cast<const float2*>(b1 + k)
                         : make_float2(0.f, 0.f);
        #pragma unroll
        for (int mt = 0; mt < 2; mt++)
            #pragma unroll
            for (int half = 0; half < 2; half++) {
                const int row = warpM * 32 + mt * 16 + half * 8 + g;
                float2 v = make_float2(acc[mt][nt][half * 2 + 0] + bv.x,
                                       acc[mt][nt][half * 2 + 1] + bv.y);
                *reinterpret_cast<float2*>(outb + (size_t)(r0 + row) * KK + k) = v;
            }
    }
}

// ---------------------------------------------------------------- persistent main kernel
// Grid = #SMs; each CTA loops over tiles (stride gridDim.x).
// Resident B: all 8 W_hu chunks preloaded in smem once (tile-invariant).
// h_c/th_s double-buffered, prefetched via cp.async during the previous tile.
// Inner loop identical to R12 (98.6% of the HMMA wall).
#define BSP    0
#define BCHUNK 20480                  // 256*ST*2 bytes per K-chunk of B
#define AS0    (BSP + 8*BCHUNK)       // 163840
#define AS1    (AS0 + 10240)          // 174080
#define RED    (AS1 + 10240)          // 184320
#define HC0    (RED + 2048)           // 186368
#define HC1    (HC0 + 1024)
#define TH0    (HC1 + 1024)
#define TH1    (TH0 + 1024)
#define W2O    (TH1 + 1024)
#define SMEM_BYTES (W2O + 1024)       // 191488

__global__ __launch_bounds__(256, 1)
void main_mma_kernel(const float* __restrict__ hmat,
                     const float* __restrict__ u,
                     const float* __restrict__ w2v,
                     const float* __restrict__ b2,
                     float* __restrict__ out)
{
    extern __shared__ char sm[];
    __half* As[2] = { reinterpret_cast<__half*>(sm + AS0), reinterpret_cast<__half*>(sm + AS1) };
    float* red    = reinterpret_cast<float*>(sm + RED);
    float* hcb[2] = { reinterpret_cast<float*>(sm + HC0), reinterpret_cast<float*>(sm + HC1) };
    float* thb[2] = { reinterpret_cast<float*>(sm + TH0), reinterpret_cast<float*>(sm + TH1) };
    float* w2_s   = reinterpret_cast<float*>(sm + W2O);

    const int tid = threadIdx.x;
    const int lid = tid & 31;
    const int wid = tid >> 5;
    const int g   = lid >> 2;
    const int t   = lid & 3;
    const int warpM = wid >> 2;      // 0..1
    const int warpN = wid & 3;       // 0..3

    const uint32_t smb = smem_u32(sm);

    // ---- one-time prologue: fill resident B (8 chunks) ----
    {
        const int br[4] = { tid >> 2, (tid + 256) >> 2, (tid + 512) >> 2, (tid + 768) >> 2 };
        const int bs = tid & 3;
        #pragma unroll
        for (int ch = 0; ch < 8; ch++)
            #pragma unroll
            for (int i = 0; i < 4; i++)
                CP_ASYNC16(smb + BSP + ch * BCHUNK + br[i] * (ST * 2) + bs * 16,
                           g_whu_h + (size_t)br[i] * HH + ch * 32 + bs * 8);
        CP_COMMIT();
    }
    // ---- first tile meta + w2 ----
    int tile = blockIdx.x;
    {
        const int bc0 = tile / 3;
        if (tid < 64)
            CP_ASYNC16(smb + HC0 + tid * 16, hmat + (size_t)bc0 * HH + tid * 4);
        else if (tid < 128)
            CP_ASYNC16(smb + TH0 + (tid - 64) * 16, g_term_h + (size_t)bc0 * KK + (tid - 64) * 4);
        else if (tid < 192)
            CP_ASYNC16(smb + W2O + (tid - 128) * 16, w2v + (tid - 128) * 4);
        CP_COMMIT();
    }
    CP_WAIT0();
    __syncthreads();
    const float b2v = b2[0];

    const int arow[4] = { tid >> 3, (tid + 256) >> 3, (tid + 512) >> 3, (tid + 768) >> 3 };
    const int ac4 = tid & 7;

    int par = 0;
    for (; tile < NTILES; tile += gridDim.x) {
        const int bc = tile / 3;
        const int qt = tile - bc * 3;
        const int b  = bc / CC;
        const int c  = bc - b * CC;
        const int q0 = qt * 128;
        const float* u_base = u + (size_t)(b * QQ + q0) * HH;
        const float* h_c  = hcb[par];
        const float* th_s = thb[par];

        float acc[4][8][4];
        #pragma unroll
        for (int mt = 0; mt < 4; mt++)
            #pragma unroll
            for (int nt = 0; nt < 8; nt++)
                #pragma unroll
                for (int e = 0; e < 4; e++) acc[mt][nt][e] = 0.f;

        auto load_A = [&](int ch, float4* aN) {
            #pragma unroll
            for (int i = 0; i < 4; i++)
                aN[i] = *reinterpret_cast<const float4*>(
                    u_base + (size_t)arow[i] * HH + ch * 32 + ac4 * 4);
        };
        auto scale_store_A = [&](int ch, float4* aN, int buf) {
            const int kb = ac4 * 4;
            float4 hv = *reinterpret_cast<const float4*>(&h_c[ch * 32 + kb]);
            #pragma unroll
            for (int i = 0; i < 4; i++) {
                float4 v = make_float4(aN[i].x * hv.x, aN[i].y * hv.y,
                                       aN[i].z * hv.z, aN[i].w * hv.w);
                *reinterpret_cast<uint2*>(&As[buf][arow[i] * ST + kb]) = pack_h4(v);
            }
        };

        // chunk 0 + next-tile meta prefetch
        {
            float4 aN[4];
            load_A(0, aN);
            const int ntile = tile + gridDim.x;
            if (ntile < NTILES) {
                const int nbc = ntile / 3;
                const uint32_t hdst = (par ? HC0 : HC1);
                const uint32_t tdst = (par ? TH0 : TH1);
                if (tid < 64)
                    CP_ASYNC16(smb + hdst + tid * 16, hmat + (size_t)nbc * HH + tid * 4);
                else if (tid < 128)
                    CP_ASYNC16(smb + tdst + (tid - 64) * 16,
                               g_term_h + (size_t)nbc * KK + (tid - 64) * 4);
                CP_COMMIT();
            }
            scale_store_A(0, aN, 0);
            __syncthreads();
        }

        for (int ch = 0; ch < 8; ch++) {
            float4 aN[4];
            if (ch < 7) load_A(ch + 1, aN);

            const uint32_t* Asu = reinterpret_cast<const uint32_t*>(As[ch & 1]);
            const uint32_t* Bsu = reinterpret_cast<const uint32_t*>(sm + BSP + ch * BCHUNK);
            #pragma unroll
            for (int s = 0; s < 2; s++) {
                const int k2 = s * 8;
                uint32_t af[4][4];
                #pragma unroll
                for (int mt = 0; mt < 4; mt++) {
                    const int r0i = (warpM * 64 + mt * 16 + g) * (ST / 2) + k2 + t;
                    af[mt][0] = Asu[r0i];
                    af[mt][1] = Asu[r0i + 8 * (ST / 2)];
                    af[mt][2] = Asu[r0i + 4];
                    af[mt][3] = Asu[r0i + 8 * (ST / 2) + 4];
                }
                #pragma unroll
                for (int nt = 0; nt < 8; nt++) {
                    const int nb = (warpN * 64 + nt * 8 + g) * (ST / 2) + k2 + t;
                    const uint32_t b0 = Bsu[nb];
                    const uint32_t b1 = Bsu[nb + 4];
                    #pragma unroll
                    for (int mt = 0; mt < 4; mt++)
                        mma16(acc[mt][nt], af[mt], b0, b1);
                }
            }

            if (ch < 7) scale_store_A(ch + 1, aN, (ch + 1) & 1);
            __syncthreads();
        }

        // ---- epilogue ----
        #pragma unroll
        for (int mt = 0; mt < 4; mt++) {
            #pragma unroll
            for (int half = 0; half < 2; half++) {
                const int row = warpM * 64 + mt * 16 + half * 8 + g;
                const int q = q0 + row;
                const float* tu = g_term_u + (size_t)(b * QQ + q) * KK;
                float s = 0.f;
                #pragma unroll
                for (int nt = 0; nt < 8; nt++) {
                    const int k = warpN * 64 + nt * 8 + 2 * t;
                    float2 tv = *reinterpret_cast<const float2*>(tu + k);
                    float v0 = acc[mt][nt][half * 2 + 0] + th_s[k]     + tv.x;
                    float v1 = acc[mt][nt][half * 2 + 1] + th_s[k + 1] + tv.y;
                    s += w2_s[k]     * lrelu(v0);
                    s += w2_s[k + 1] * lrelu(v1);
                }
                s += __shfl_xor_sync(0xffffffffu, s, 1);
                s += __shfl_xor_sync(0xffffffffu, s, 2);
                if (t == 0) red[warpN * 128 + row] = s;
            }
        }
        CP_WAIT0();            // next-tile meta arrival
        __syncthreads();       // red + meta visible to all
        if (tid < 128) {
            float s = red[tid] + red[128 + tid] + red[256 + tid] + red[384 + tid] + b2v;
            out[(size_t)bc * QQ + q0 + tid] = lrelu(s);
        }
        par ^= 1;
    }
}

// ---------------------------------------------------------------- launch
extern "C" void kernel_launch(void* const* d_in, const int* in_sizes, int n_in,
                              void* d_out, int out_size) {
    (void)in_sizes; (void)n_in; (void)out_size;
    const float* h_  = (const float*)d_in[0];
    const float* u_  = (const float*)d_in[1];
    const float* w1_ = (const float*)d_in[2];
    const float* b1_ = (const float*)d_in[3];
    const float* w2_ = (const float*)d_in[4];
    const float* b2_ = (const float*)d_in[5];
    float* out_ = (float*)d_out;

    int dev = 0, nsm = 148;
    cudaGetDevice(&dev);
    cudaDeviceGetAttribute(&nsm, cudaDevAttrMultiProcessorCount, dev);

    cudaFuncSetAttribute(main_mma_kernel,
                         cudaFuncAttributeMaxDynamicSharedMemorySize, SMEM_BYTES);

    prep_mma_kernel<<<112, 256>>>(h_, u_, w1_, b1_);
    main_mma_kernel<<<nsm, 256, SMEM_BYTES>>>(h_, u_, w2_, b2_, out_);
}

// round 15
// speedup vs baseline: 1.8395x; 1.0494x over previous
#include <cuda_runtime.h>
#include <cuda_fp16.h>
#include <cstdint>

#define BB 4
#define CC 384
#define QQ 384
#define HH 256
#define KK 256

#define ST 40                 // smem row stride in halves (80B)
#define NTILES (BB*CC*3)      // 4608 q-tiles of 128

// ---------------------------------------------------------------- scratch
__device__ float g_term_h[BB*CC*KK];                 // term_h + b1
__device__ float g_term_u[BB*QQ*KK];                 // term_u
__device__ __align__(16) __half g_whu_h[KK*HH];      // W_hu fp16, [k][h] dense

__device__ __forceinline__ float lrelu(float x) {
    return fmaxf(x, 0.f) + 0.01f * fminf(x, 0.f);
}
__device__ __forceinline__ void mma16(float* d, const uint32_t* a, uint32_t b0, uint32_t b1) {
    asm volatile("mma.sync.aligned.m16n8k16.row.col.f32.f16.f16.f32 "
                 "{%0,%1,%2,%3}, {%4,%5,%6,%7}, {%8,%9}, {%0,%1,%2,%3};"
                 : "+f"(d[0]), "+f"(d[1]), "+f"(d[2]), "+f"(d[3])
                 : "r"(a[0]), "r"(a[1]), "r"(a[2]), "r"(a[3]), "r"(b0), "r"(b1));
}
__device__ __forceinline__ uint32_t smem_u32(const void* p) {
    uint32_t a;
    asm("{ .reg .u64 t; cvta.to.shared.u64 t, %1; cvt.u32.u64 %0, t; }" : "=r"(a) : "l"(p));
    return a;
}
#define CP_ASYNC16(dst, src) \
    asm volatile("cp.async.cg.shared.global [%0], [%1], 16;" :: "r"(dst), "l"(src))
#define CP_COMMIT() asm volatile("cp.async.commit_group;" ::: "memory")
#define CP_WAIT0()  asm volatile("cp.async.wait_group 0;"  ::: "memory")

__device__ __forceinline__ uint2 pack_h4(float4 v) {
    __half2 p0 = __floats2half2_rn(v.x, v.y);
    __half2 p1 = __floats2half2_rn(v.z, v.w);
    return make_uint2(*reinterpret_cast<uint32_t*>(&p0), *reinterpret_cast<uint32_t*>(&p1));
}

// ---------------------------------------------------------------- tensor-core prep kernel
// (R13 configuration — measured ~7.3us. UNCHANGED.)
__global__ __launch_bounds__(256)
void prep_mma_kernel(const float* __restrict__ h, const float* __restrict__ u,
                     const float* __restrict__ w1, const float* __restrict__ b1) {
    const int blk = blockIdx.x;
    const int tid = threadIdx.x;

    if (blk >= 48) {   // ---- pack W_hu ----
        const int k0 = (blk - 48) * 4;
        #pragma unroll
        for (int r = 0; r < 4; r++)
            g_whu_h[(k0 + r) * HH + tid] =
                __float2half_rn(w1[(size_t)(k0 + r) * (3 * HH) + 2 * HH + tid]);
        return;
    }

    __shared__ __half As_[64 * ST];
    __shared__ __half Bs_[256 * ST];

    const bool is_h = blk < 24;
    const int r0 = (is_h ? blk : blk - 24) * 64;
    const float* x = is_h ? h : u;
    float* outb = is_h ? g_term_h : g_term_u;
    const int coloff = is_h ? 0 : HH;

    const int lid = tid & 31;
    const int wid = tid >> 5;
    const int g   = lid >> 2;
    const int t   = lid & 3;
    const int warpM = wid >> 2;
    const int warpN = wid & 3;

    float acc[2][8][4];
    #pragma unroll
    for (int mt = 0; mt < 2; mt++)
        #pragma unroll
        for (int nt = 0; nt < 8; nt++)
            #pragma unroll
            for (int e = 0; e < 4; e++) acc[mt][nt][e] = 0.f;

    for (int ch = 0; ch < 8; ch++) {
        #pragma unroll
        for (int i = 0; i < 2; i++) {
            const int idx = tid + i * 256;
            const int row = idx >> 3, c4 = idx & 7;
            float4 v = *reinterpret_cast<const float4*>(
                x + (size_t)(r0 + row) * HH + ch * 32 + c4 * 4);
            *reinterpret_cast<uint2*>(&As_[row * ST + c4 * 4]) = pack_h4(v);
        }
        #pragma unroll
        for (int i = 0; i < 8; i++) {
            const int idx = tid + i * 256;
            const int row = idx >> 3, c4 = idx & 7;
            float4 v = *reinterpret_cast<const float4*>(
                w1 + (size_t)row * (3 * HH) + coloff + ch * 32 + c4 * 4);
            *reinterpret_cast<uint2*>(&Bs_[row * ST + c4 * 4]) = pack_h4(v);
        }
        __syncthreads();

        const uint32_t* Asu = reinterpret_cast<const uint32_t*>(As_);
        const uint32_t* Bsu = reinterpret_cast<const uint32_t*>(Bs_);
        #pragma unroll
        for (int s = 0; s < 2; s++) {
            const int k2 = s * 8;
            uint32_t af[2][4];
            #pragma unroll
            for (int mt = 0; mt < 2; mt++) {
                const int r0i = (warpM * 32 + mt * 16 + g) * (ST / 2) + k2 + t;
                af[mt][0] = Asu[r0i];
                af[mt][1] = Asu[r0i + 8 * (ST / 2)];
                af[mt][2] = Asu[r0i + 4];
                af[mt][3] = Asu[r0i + 8 * (ST / 2) + 4];
            }
            #pragma unroll
            for (int nt = 0; nt < 8; nt++) {
                const int nb = (warpN * 64 + nt * 8 + g) * (ST / 2) + k2 + t;
                const uint32_t b0 = Bsu[nb];
                const uint32_t b1r = Bsu[nb + 4];
                #pragma unroll
                for (int mt = 0; mt < 2; mt++)
                    mma16(acc[mt][nt], af[mt], b0, b1r);
            }
        }
        __syncthreads();
    }

    #pragma unroll
    for (int nt = 0; nt < 8; nt++) {
        const int k = warpN * 64 + nt * 8 + 2 * t;
        float2 bv = is_h ? *reinterpret_cast<const float2*>(b1 + k)
                         : make_float2(0.f, 0.f);
        #pragma unroll
        for (int mt = 0; mt < 2; mt++)
            #pragma unroll
            for (int half = 0; half < 2; half++) {
                const int row = warpM * 32 + mt * 16 + half * 8 + g;
                float2 v = make_float2(acc[mt][nt][half * 2 + 0] + bv.x,
                                       acc[mt][nt][half * 2 + 1] + bv.y);
                *reinterpret_cast<float2*>(outb + (size_t)(r0 + row) * KK + k) = v;
            }
    }
}

// ---------------------------------------------------------------- persistent main kernel
// Each CTA: exactly NTILES/G full tiles (M=128) + optionally one half-tile (M=64)
// from the remainder — balances the wave (was 30/31 split costing ~2.3%).
// Resident B (8 chunks, tile-invariant); meta double-buffered via cp.async.
#define BSP    0
#define BCHUNK 20480                  // 256*ST*2 bytes per K-chunk of B
#define AS0    (BSP + 8*BCHUNK)       // 163840
#define AS1    (AS0 + 10240)          // 174080
#define RED    (AS1 + 10240)          // 184320
#define HC0    (RED + 2048)           // 186368
#define HC1    (HC0 + 1024)
#define TH0    (HC1 + 1024)
#define TH1    (TH0 + 1024)
#define W2O    (TH1 + 1024)
#define SMEM_BYTES (W2O + 1024)       // 191488

__global__ __launch_bounds__(256, 1)
void main_mma_kernel(const float* __restrict__ hmat,
                     const float* __restrict__ u,
                     const float* __restrict__ w2v,
                     const float* __restrict__ b2,
                     float* __restrict__ out)
{
    extern __shared__ char sm[];
    __half* As[2] = { reinterpret_cast<__half*>(sm + AS0), reinterpret_cast<__half*>(sm + AS1) };
    float* red    = reinterpret_cast<float*>(sm + RED);
    float* hcb[2] = { reinterpret_cast<float*>(sm + HC0), reinterpret_cast<float*>(sm + HC1) };
    float* thb[2] = { reinterpret_cast<float*>(sm + TH0), reinterpret_cast<float*>(sm + TH1) };
    float* w2_s   = reinterpret_cast<float*>(sm + W2O);

    const int tid = threadIdx.x;
    const int lid = tid & 31;
    const int wid = tid >> 5;
    const int g   = lid >> 2;
    const int t   = lid & 3;
    const int warpM = wid >> 2;      // 0..1
    const int warpN = wid & 3;       // 0..3

    const int G     = gridDim.x;
    const int NPER  = NTILES / G;          // full tiles per CTA
    const int NFULL = NPER * G;
    const int NREM2 = 2 * (NTILES - NFULL);  // # of half-tiles

    const uint32_t smb = smem_u32(sm);

    // ---- one-time prologue: fill resident B (8 chunks) ----
    {
        const int br[4] = { tid >> 2, (tid + 256) >> 2, (tid + 512) >> 2, (tid + 768) >> 2 };
        const int bs = tid & 3;
        #pragma unroll
        for (int ch = 0; ch < 8; ch++)
            #pragma unroll
            for (int i = 0; i < 4; i++)
                CP_ASYNC16(smb + BSP + ch * BCHUNK + br[i] * (ST * 2) + bs * 16,
                           g_whu_h + (size_t)br[i] * HH + ch * 32 + bs * 8);
        CP_COMMIT();
    }
    // ---- first tile meta + w2 ----
    {
        const int bc0 = blockIdx.x / 3;
        if (tid < 64)
            CP_ASYNC16(smb + HC0 + tid * 16, hmat + (size_t)bc0 * HH + tid * 4);
        else if (tid < 128)
            CP_ASYNC16(smb + TH0 + (tid - 64) * 16, g_term_h + (size_t)bc0 * KK + (tid - 64) * 4);
        else if (tid < 192)
            CP_ASYNC16(smb + W2O + (tid - 128) * 16, w2v + (tid - 128) * 4);
        CP_COMMIT();
    }
    CP_WAIT0();
    __syncthreads();
    const float b2v = b2[0];

    const int arow[4] = { tid >> 3, (tid + 256) >> 3, (tid + 512) >> 3, (tid + 768) >> 3 };
    const int ac4 = tid & 7;

    int par = 0;
    for (int w = 0; w < NPER; w++) {
        const int tile = blockIdx.x + w * G;
        const int bc = tile / 3;
        const int qt = tile - bc * 3;
        const int b  = bc / CC;
        const int q0 = qt * 128;
        const float* u_base = u + (size_t)(b * QQ + q0) * HH;
        const float* h_c  = hcb[par];
        const float* th_s = thb[par];

        float acc[4][8][4];
        #pragma unroll
        for (int mt = 0; mt < 4; mt++)
            #pragma unroll
            for (int nt = 0; nt < 8; nt++)
                #pragma unroll
                for (int e = 0; e < 4; e++) acc[mt][nt][e] = 0.f;

        auto load_A = [&](int ch, float4* aN) {
            #pragma unroll
            for (int i = 0; i < 4; i++)
                aN[i] = *reinterpret_cast<const float4*>(
                    u_base + (size_t)arow[i] * HH + ch * 32 + ac4 * 4);
        };
        auto scale_store_A = [&](int ch, float4* aN, int buf) {
            const int kb = ac4 * 4;
            float4 hv = *reinterpret_cast<const float4*>(&h_c[ch * 32 + kb]);
            #pragma unroll
            for (int i = 0; i < 4; i++) {
                float4 v = make_float4(aN[i].x * hv.x, aN[i].y * hv.y,
                                       aN[i].z * hv.z, aN[i].w * hv.w);
                *reinterpret_cast<uint2*>(&As[buf][arow[i] * ST + kb]) = pack_h4(v);
            }
        };

        // chunk 0 + next meta prefetch (next full tile, or this CTA's half-tile)
        {
            float4 aN[4];
            load_A(0, aN);
            int nbc = -1;
            if (w < NPER - 1)               nbc = (tile + G) / 3;
            else if (blockIdx.x < NREM2)    nbc = (NFULL + (blockIdx.x >> 1)) / 3;
            if (nbc >= 0) {
                const uint32_t hdst = (par ? HC0 : HC1);
                const uint32_t tdst = (par ? TH0 : TH1);
                if (tid < 64)
                    CP_ASYNC16(smb + hdst + tid * 16, hmat + (size_t)nbc * HH + tid * 4);
                else if (tid < 128)
                    CP_ASYNC16(smb + tdst + (tid - 64) * 16,
                               g_term_h + (size_t)nbc * KK + (tid - 64) * 4);
                CP_COMMIT();
            }
            scale_store_A(0, aN, 0);
            __syncthreads();
        }

        for (int ch = 0; ch < 8; ch++) {
            float4 aN[4];
            if (ch < 7) load_A(ch + 1, aN);

            const uint32_t* Asu = reinterpret_cast<const uint32_t*>(As[ch & 1]);
            const uint32_t* Bsu = reinterpret_cast<const uint32_t*>(sm + BSP + ch * BCHUNK);
            #pragma unroll
            for (int s = 0; s < 2; s++) {
                const int k2 = s * 8;
                uint32_t af[4][4];
                #pragma unroll
                for (int mt = 0; mt < 4; mt++) {
                    const int r0i = (warpM * 64 + mt * 16 + g) * (ST / 2) + k2 + t;
                    af[mt][0] = Asu[r0i];
                    af[mt][1] = Asu[r0i + 8 * (ST / 2)];
                    af[mt][2] = Asu[r0i + 4];
                    af[mt][3] = Asu[r0i + 8 * (ST / 2) + 4];
                }
                #pragma unroll
                for (int nt = 0; nt < 8; nt++) {
                    const int nb = (warpN * 64 + nt * 8 + g) * (ST / 2) + k2 + t;
                    const uint32_t b0 = Bsu[nb];
                    const uint32_t b1 = Bsu[nb + 4];
                    #pragma unroll
                    for (int mt = 0; mt < 4; mt++)
                        mma16(acc[mt][nt], af[mt], b0, b1);
                }
            }

            if (ch < 7) scale_store_A(ch + 1, aN, (ch + 1) & 1);
            __syncthreads();
        }

        // ---- epilogue ----
        #pragma unroll
        for (int mt = 0; mt < 4; mt++) {
            #pragma unroll
            for (int half = 0; half < 2; half++) {
                const int row = warpM * 64 + mt * 16 + half * 8 + g;
                const int q = q0 + row;
                const float* tu = g_term_u + (size_t)(b * QQ + q) * KK;
                float s = 0.f;
                #pragma unroll
                for (int nt = 0; nt < 8; nt++) {
                    const int k = warpN * 64 + nt * 8 + 2 * t;
                    float2 tv = *reinterpret_cast<const float2*>(tu + k);
                    float v0 = acc[mt][nt][half * 2 + 0] + th_s[k]     + tv.x;
                    float v1 = acc[mt][nt][half * 2 + 1] + th_s[k + 1] + tv.y;
                    s += w2_s[k]     * lrelu(v0);
                    s += w2_s[k + 1] * lrelu(v1);
                }
                s += __shfl_xor_sync(0xffffffffu, s, 1);
                s += __shfl_xor_sync(0xffffffffu, s, 2);
                if (t == 0) red[warpN * 128 + row] = s;
            }
        }
        CP_WAIT0();
        __syncthreads();
        if (tid < 128) {
            float s = red[tid] + red[128 + tid] + red[256 + tid] + red[384 + tid] + b2v;
            out[(size_t)bc * QQ + q0 + tid] = lrelu(s);
        }
        par ^= 1;
    }

    // ---- remainder: one half-tile (M=64) for CTAs [0, NREM2) ----
    if (blockIdx.x < NREM2) {
        const int tile = NFULL + (blockIdx.x >> 1);
        const int m0 = (blockIdx.x & 1) * 64;
        const int bc = tile / 3;
        const int qt = tile - bc * 3;
        const int b  = bc / CC;
        const int q0 = qt * 128 + m0;        // 64-row block
        const float* u_base = u + (size_t)(b * QQ + q0) * HH;
        const float* h_c  = hcb[par];
        const float* th_s = thb[par];

        const int arow2[2] = { tid >> 3, (tid + 256) >> 3 };

        float acc[2][8][4];
        #pragma unroll
        for (int mt = 0; mt < 2; mt++)
            #pragma unroll
            for (int nt = 0; nt < 8; nt++)
                #pragma unroll
                for (int e = 0; e < 4; e++) acc[mt][nt][e] = 0.f;

        auto load_A2 = [&](int ch, float4* aN) {
            #pragma unroll
            for (int i = 0; i < 2; i++)
                aN[i] = *reinterpret_cast<const float4*>(
                    u_base + (size_t)arow2[i] * HH + ch * 32 + ac4 * 4);
        };
        auto scale_store_A2 = [&](int ch, float4* aN, int buf) {
            const int kb = ac4 * 4;
            float4 hv = *reinterpret_cast<const float4*>(&h_c[ch * 32 + kb]);
            #pragma unroll
            for (int i = 0; i < 2; i++) {
                float4 v = make_float4(aN[i].x * hv.x, aN[i].y * hv.y,
                                       aN[i].z * hv.z, aN[i].w * hv.w);
                *reinterpret_cast<uint2*>(&As[buf][arow2[i] * ST + kb]) = pack_h4(v);
            }
        };

        {
            float4 aN[2];
            load_A2(0, aN);
            scale_store_A2(0, aN, 0);
            __syncthreads();
        }

        for (int ch = 0; ch < 8; ch++) {
            float4 aN[2];
            if (ch < 7) load_A2(ch + 1, aN);

            const uint32_t* Asu = reinterpret_cast<const uint32_t*>(As[ch & 1]);
            const uint32_t* Bsu = reinterpret_cast<const uint32_t*>(sm + BSP + ch * BCHUNK);
            #pragma unroll
            for (int s = 0; s < 2; s++) {
                const int k2 = s * 8;
                uint32_t af[2][4];
                #pragma unroll
                for (int mt = 0; mt < 2; mt++) {
                    const int r0i = (warpM * 32 + mt * 16 + g) * (ST / 2) + k2 + t;
                    af[mt][0] = Asu[r0i];
                    af[mt][1] = Asu[r0i + 8 * (ST / 2)];
                    af[mt][2] = Asu[r0i + 4];
                    af[mt][3] = Asu[r0i + 8 * (ST / 2) + 4];
                }
                #pragma unroll
                for (int nt = 0; nt < 8; nt++) {
                    const int nb = (warpN * 64 + nt * 8 + g) * (ST / 2) + k2 + t;
                    const uint32_t b0 = Bsu[nb];
                    const uint32_t b1 = Bsu[nb + 4];
                    #pragma unroll
                    for (int mt = 0; mt < 2; mt++)
                        mma16(acc[mt][nt], af[mt], b0, b1);
                }
            }

            if (ch < 7) scale_store_A2(ch + 1, aN, (ch + 1) & 1);
            __syncthreads();
        }

        #pragma unroll
        for (int mt = 0; mt < 2; mt++) {
            #pragma unroll
            for (int half = 0; half < 2; half++) {
                const int row = warpM * 32 + mt * 16 + half * 8 + g;
                const int q = q0 + row;
                const float* tu = g_term_u + (size_t)(b * QQ + q) * KK;
                float s = 0.f;
                #pragma unroll
                for (int nt = 0; nt < 8; nt++) {
                    const int k = warpN * 64 + nt * 8 + 2 * t;
                    float2 tv = *reinterpret_cast<const float2*>(tu + k);
                    float v0 = acc[mt][nt][half * 2 + 0] + th_s[k]     + tv.x;
                    float v1 = acc[mt][nt][half * 2 + 1] + th_s[k + 1] + tv.y;
                    s += w2_s[k]     * lrelu(v0);
                    s += w2_s[k + 1] * lrelu(v1);
                }
                s += __shfl_xor_sync(0xffffffffu, s, 1);
                s += __shfl_xor_sync(0xffffffffu, s, 2);
                if (t == 0) red[warpN * 64 + row] = s;
            }
        }
        __syncthreads();
        if (tid < 64) {
            float s = red[tid] + red[64 + tid] + red[128 + tid] + red[192 + tid] + b2v;
            out[(size_t)bc * QQ + q0 + tid] = lrelu(s);
        }
    }
}

// ---------------------------------------------------------------- launch
extern "C" void kernel_launch(void* const* d_in, const int* in_sizes, int n_in,
                              void* d_out, int out_size) {
    (void)in_sizes; (void)n_in; (void)out_size;
    const float* h_  = (const float*)d_in[0];
    const float* u_  = (const float*)d_in[1];
    const float* w1_ = (const float*)d_in[2];
    const float* b1_ = (const float*)d_in[3];
    const float* w2_ = (const float*)d_in[4];
    const float* b2_ = (const float*)d_in[5];
    float* out_ = (float*)d_out;

    int dev = 0, nsm = 148;
    cudaGetDevice(&dev);
    cudaDeviceGetAttribute(&nsm, cudaDevAttrMultiProcessorCount, dev);

    cudaFuncSetAttribute(main_mma_kernel,
                         cudaFuncAttributeMaxDynamicSharedMemorySize, SMEM_BYTES);

    prep_mma_kernel<<<112, 256>>>(h_, u_, w1_, b1_);
    main_mma_kernel<<<nsm, 256, SMEM_BYTES>>>(h_, u_, w2_, b2_, out_);
}

// round 16
// speedup vs baseline: 2.1049x; 1.1443x over previous
#include <cuda_runtime.h>
#include <cuda_fp16.h>
#include <cstdint>

#define BB 4
#define CC 384
#define QQ 384
#define HH 256
#define KK 256

#define ST 40                 // smem row stride in halves (80B)
#define NTILES (BB*CC*3)      // 4608 q-tiles of 128

// ---------------------------------------------------------------- scratch
__device__ float g_term_h[BB*CC*KK];                 // term_h + b1
__device__ float g_term_u[BB*QQ*KK];                 // term_u
__device__ __align__(16) __half g_whu_h[KK*HH];      // W_hu fp16, [k][h] dense

__device__ __forceinline__ float lrelu(float x) {
    return fmaxf(x, 0.f) + 0.01f * fminf(x, 0.f);
}
__device__ __forceinline__ void mma16(float* d, const uint32_t* a, uint32_t b0, uint32_t b1) {
    asm volatile("mma.sync.aligned.m16n8k16.row.col.f32.f16.f16.f32 "
                 "{%0,%1,%2,%3}, {%4,%5,%6,%7}, {%8,%9}, {%0,%1,%2,%3};"
                 : "+f"(d[0]), "+f"(d[1]), "+f"(d[2]), "+f"(d[3])
                 : "r"(a[0]), "r"(a[1]), "r"(a[2]), "r"(a[3]), "r"(b0), "r"(b1));
}
__device__ __forceinline__ uint32_t smem_u32(const void* p) {
    uint32_t a;
    asm("{ .reg .u64 t; cvta.to.shared.u64 t, %1; cvt.u32.u64 %0, t; }" : "=r"(a) : "l"(p));
    return a;
}
#define CP_ASYNC16(dst, src) \
    asm volatile("cp.async.cg.shared.global [%0], [%1], 16;" :: "r"(dst), "l"(src))
#define CP_COMMIT() asm volatile("cp.async.commit_group;" ::: "memory")
#define CP_WAIT0()  asm volatile("cp.async.wait_group 0;"  ::: "memory")
#define BAR_HALF(id) asm volatile("bar.sync %0, 128;" :: "r"(id) : "memory")

__device__ __forceinline__ uint2 pack_h4(float4 v) {
    __half2 p0 = __floats2half2_rn(v.x, v.y);
    __half2 p1 = __floats2half2_rn(v.z, v.w);
    return make_uint2(*reinterpret_cast<uint32_t*>(&p0), *reinterpret_cast<uint32_t*>(&p1));
}

// ---------------------------------------------------------------- tensor-core prep kernel
// Pipelined: next-chunk LDGs hoisted into registers before each MMA block.
__global__ __launch_bounds__(256)
void prep_mma_kernel(const float* __restrict__ h, const float* __restrict__ u,
                     const float* __restrict__ w1, const float* __restrict__ b1) {
    const int blk = blockIdx.x;
    const int tid = threadIdx.x;

    if (blk >= 48) {   // ---- pack W_hu ----
        const int k0 = (blk - 48) * 4;
        #pragma unroll
        for (int r = 0; r < 4; r++)
            g_whu_h[(k0 + r) * HH + tid] =
                __float2half_rn(w1[(size_t)(k0 + r) * (3 * HH) + 2 * HH + tid]);
        return;
    }

    __shared__ __half As_[64 * ST];
    __shared__ __half Bs_[256 * ST];

    const bool is_h = blk < 24;
    const int r0 = (is_h ? blk : blk - 24) * 64;
    const float* x = is_h ? h : u;
    float* outb = is_h ? g_term_h : g_term_u;
    const int coloff = is_h ? 0 : HH;

    const int lid = tid & 31;
    const int wid = tid >> 5;
    const int g   = lid >> 2;
    const int t   = lid & 3;
    const int warpM = wid >> 2;
    const int warpN = wid & 3;

    float acc[2][8][4];
    #pragma unroll
    for (int mt = 0; mt < 2; mt++)
        #pragma unroll
        for (int nt = 0; nt < 8; nt++)
            #pragma unroll
            for (int e = 0; e < 4; e++) acc[mt][nt][e] = 0.f;

    const int ar = tid >> 3, ac4 = tid & 7;           // A segs (2 iters)
    const int ar2 = (tid + 256) >> 3;
    float4 aR[2], bR[8];

    auto load_regs = [&](int ch) {
        aR[0] = *reinterpret_cast<const float4*>(x + (size_t)(r0 + ar) * HH + ch * 32 + ac4 * 4);
        aR[1] = *reinterpret_cast<const float4*>(x + (size_t)(r0 + ar2) * HH + ch * 32 + ac4 * 4);
        #pragma unroll
        for (int i = 0; i < 8; i++) {
            const int idx = tid + i * 256;
            const int row = idx >> 3, c4 = idx & 7;
            bR[i] = *reinterpret_cast<const float4*>(
                w1 + (size_t)row * (3 * HH) + coloff + ch * 32 + c4 * 4);
        }
    };
    auto store_regs = [&]() {
        *reinterpret_cast<uint2*>(&As_[ar  * ST + ac4 * 4]) = pack_h4(aR[0]);
        *reinterpret_cast<uint2*>(&As_[ar2 * ST + ac4 * 4]) = pack_h4(aR[1]);
        #pragma unroll
        for (int i = 0; i < 8; i++) {
            const int idx = tid + i * 256;
            const int row = idx >> 3, c4 = idx & 7;
            *reinterpret_cast<uint2*>(&Bs_[row * ST + c4 * 4]) = pack_h4(bR[i]);
        }
    };

    load_regs(0);
    store_regs();
    __syncthreads();

    for (int ch = 0; ch < 8; ch++) {
        if (ch < 7) load_regs(ch + 1);   // overlap LDG latency with MMAs

        const uint32_t* Asu = reinterpret_cast<const uint32_t*>(As_);
        const uint32_t* Bsu = reinterpret_cast<const uint32_t*>(Bs_);
        #pragma unroll
        for (int s = 0; s < 2; s++) {
            const int k2 = s * 8;
            uint32_t af[2][4];
            #pragma unroll
            for (int mt = 0; mt < 2; mt++) {
                const int r0i = (warpM * 32 + mt * 16 + g) * (ST / 2) + k2 + t;
                af[mt][0] = Asu[r0i];
                af[mt][1] = Asu[r0i + 8 * (ST / 2)];
                af[mt][2] = Asu[r0i + 4];
                af[mt][3] = Asu[r0i + 8 * (ST / 2) + 4];
            }
            #pragma unroll
            for (int nt = 0; nt < 8; nt++) {
                const int nb = (warpN * 64 + nt * 8 + g) * (ST / 2) + k2 + t;
                const uint32_t b0 = Bsu[nb];
                const uint32_t b1r = Bsu[nb + 4];
                #pragma unroll
                for (int mt = 0; mt < 2; mt++)
                    mma16(acc[mt][nt], af[mt], b0, b1r);
            }
        }
        __syncthreads();
        if (ch < 7) {
            store_regs();
            __syncthreads();
        }
    }

    #pragma unroll
    for (int nt = 0; nt < 8; nt++) {
        const int k = warpN * 64 + nt * 8 + 2 * t;
        float2 bv = is_h ? *reinterpret_cast<const float2*>(b1 + k)
                         : make_float2(0.f, 0.f);
        #pragma unroll
        for (int mt = 0; mt < 2; mt++)
            #pragma unroll
            for (int half = 0; half < 2; half++) {
                const int row = warpM * 32 + mt * 16 + half * 8 + g;
                float2 v = make_float2(acc[mt][nt][half * 2 + 0] + bv.x,
                                       acc[mt][nt][half * 2 + 1] + bv.y);
                *reinterpret_cast<float2*>(outb + (size_t)(r0 + row) * KK + k) = v;
            }
    }
}

// ---------------------------------------------------------------- persistent main kernel
// Balanced tiles + tail half-tiles; resident B; meta double-buffered.
// NEW: split half-CTA barriers — warps 0-3 own A rows 0-63, warps 4-7 rows 64-127;
// per-chunk sync is bar.sync 1/2 over 128 threads (only A is chunk-mutable).
#define BSP    0
#define BCHUNK 20480                  // 256*ST*2 bytes per K-chunk of B
#define AS0    (BSP + 8*BCHUNK)       // 163840
#define AS1    (AS0 + 10240)          // 174080
#define RED    (AS1 + 10240)          // 184320
#define HC0    (RED + 2048)           // 186368
#define HC1    (HC0 + 1024)
#define TH0    (HC1 + 1024)
#define TH1    (TH0 + 1024)
#define W2O    (TH1 + 1024)
#define SMEM_BYTES (W2O + 1024)       // 191488

__global__ __launch_bounds__(256, 1)
void main_mma_kernel(const float* __restrict__ hmat,
                     const float* __restrict__ u,
                     const float* __restrict__ w2v,
                     const float* __restrict__ b2,
                     float* __restrict__ out)
{
    extern __shared__ char sm[];
    __half* As[2] = { reinterpret_cast<__half*>(sm + AS0), reinterpret_cast<__half*>(sm + AS1) };
    float* red    = reinterpret_cast<float*>(sm + RED);
    float* hcb[2] = { reinterpret_cast<float*>(sm + HC0), reinterpret_cast<float*>(sm + HC1) };
    float* thb[2] = { reinterpret_cast<float*>(sm + TH0), reinterpret_cast<float*>(sm + TH1) };
    float* w2_s   = reinterpret_cast<float*>(sm + W2O);

    const int tid = threadIdx.x;
    const int lid = tid & 31;
    const int wid = tid >> 5;
    const int g   = lid >> 2;
    const int t   = lid & 3;
    const int warpM = wid >> 2;      // 0..1  (== tid>>7, the CTA half)
    const int warpN = wid & 3;       // 0..3
    const int halfid = tid >> 7;     // 0 or 1
    const int ht  = tid & 127;
    const int barid = 1 + halfid;

    const int G     = gridDim.x;
    const int NPER  = NTILES / G;
    const int NFULL = NPER * G;
    const int NREM2 = 2 * (NTILES - NFULL);

    const uint32_t smb = smem_u32(sm);

    // ---- one-time prologue: fill resident B (8 chunks) ----
    {
        const int br[4] = { tid >> 2, (tid + 256) >> 2, (tid + 512) >> 2, (tid + 768) >> 2 };
        const int bs = tid & 3;
        #pragma unroll
        for (int ch = 0; ch < 8; ch++)
            #pragma unroll
            for (int i = 0; i < 4; i++)
                CP_ASYNC16(smb + BSP + ch * BCHUNK + br[i] * (ST * 2) + bs * 16,
                           g_whu_h + (size_t)br[i] * HH + ch * 32 + bs * 8);
        CP_COMMIT();
    }
    // ---- first tile meta + w2 ----
    {
        const int bc0 = blockIdx.x / 3;
        if (tid < 64)
            CP_ASYNC16(smb + HC0 + tid * 16, hmat + (size_t)bc0 * HH + tid * 4);
        else if (tid < 128)
            CP_ASYNC16(smb + TH0 + (tid - 64) * 16, g_term_h + (size_t)bc0 * KK + (tid - 64) * 4);
        else if (tid < 192)
            CP_ASYNC16(smb + W2O + (tid - 128) * 16, w2v + (tid - 128) * 4);
        CP_COMMIT();
    }
    CP_WAIT0();
    __syncthreads();
    const float b2v = b2[0];

    // A-load coords: each CTA-half owns its 64 rows (halfid*64 .. +63)
    const int arow[4] = { halfid * 64 + ((ht          ) >> 3),
                          halfid * 64 + ((ht + 128    ) >> 3),
                          halfid * 64 + ((ht + 256    ) >> 3),
                          halfid * 64 + ((ht + 384    ) >> 3) };
    const int ac4 = ht & 7;

    int par = 0;
    for (int w = 0; w < NPER; w++) {
        const int tile = blockIdx.x + w * G;
        const int bc = tile / 3;
        const int qt = tile - bc * 3;
        const int b  = bc / CC;
        const int q0 = qt * 128;
        const float* u_base = u + (size_t)(b * QQ + q0) * HH;
        const float* h_c  = hcb[par];
        const float* th_s = thb[par];

        float acc[4][8][4];
        #pragma unroll
        for (int mt = 0; mt < 4; mt++)
            #pragma unroll
            for (int nt = 0; nt < 8; nt++)
                #pragma unroll
                for (int e = 0; e < 4; e++) acc[mt][nt][e] = 0.f;

        auto load_A = [&](int ch, float4* aN) {
            #pragma unroll
            for (int i = 0; i < 4; i++)
                aN[i] = *reinterpret_cast<const float4*>(
                    u_base + (size_t)arow[i] * HH + ch * 32 + ac4 * 4);
        };
        auto scale_store_A = [&](int ch, float4* aN, int buf) {
            const int kb = ac4 * 4;
            float4 hv = *reinterpret_cast<const float4*>(&h_c[ch * 32 + kb]);
            #pragma unroll
            for (int i = 0; i < 4; i++) {
                float4 v = make_float4(aN[i].x * hv.x, aN[i].y * hv.y,
                                       aN[i].z * hv.z, aN[i].w * hv.w);
                *reinterpret_cast<uint2*>(&As[buf][arow[i] * ST + kb]) = pack_h4(v);
            }
        };

        // chunk 0 + next meta prefetch
        {
            float4 aN[4];
            load_A(0, aN);
            int nbc = -1;
            if (w < NPER - 1)               nbc = (tile + G) / 3;
            else if (blockIdx.x < NREM2)    nbc = (NFULL + (blockIdx.x >> 1)) / 3;
            if (nbc >= 0) {
                const uint32_t hdst = (par ? HC0 : HC1);
                const uint32_t tdst = (par ? TH0 : TH1);
                if (tid < 64)
                    CP_ASYNC16(smb + hdst + tid * 16, hmat + (size_t)nbc * HH + tid * 4);
                else if (tid < 128)
                    CP_ASYNC16(smb + tdst + (tid - 64) * 16,
                               g_term_h + (size_t)nbc * KK + (tid - 64) * 4);
                CP_COMMIT();
            }
            scale_store_A(0, aN, 0);
            BAR_HALF(barid);
        }

        for (int ch = 0; ch < 8; ch++) {
            float4 aN[4];
            if (ch < 7) load_A(ch + 1, aN);

            const uint32_t* Asu = reinterpret_cast<const uint32_t*>(As[ch & 1]);
            const uint32_t* Bsu = reinterpret_cast<const uint32_t*>(sm + BSP + ch * BCHUNK);
            #pragma unroll
            for (int s = 0; s < 2; s++) {
                const int k2 = s * 8;
                uint32_t af[4][4];
                #pragma unroll
                for (int mt = 0; mt < 4; mt++) {
                    const int r0i = (warpM * 64 + mt * 16 + g) * (ST / 2) + k2 + t;
                    af[mt][0] = Asu[r0i];
                    af[mt][1] = Asu[r0i + 8 * (ST / 2)];
                    af[mt][2] = Asu[r0i + 4];
                    af[mt][3] = Asu[r0i + 8 * (ST / 2) + 4];
                }
                #pragma unroll
                for (int nt = 0; nt < 8; nt++) {
                    const int nb = (warpN * 64 + nt * 8 + g) * (ST / 2) + k2 + t;
                    const uint32_t b0 = Bsu[nb];
                    const uint32_t b1 = Bsu[nb + 4];
                    #pragma unroll
                    for (int mt = 0; mt < 4; mt++)
                        mma16(acc[mt][nt], af[mt], b0, b1);
                }
            }

            if (ch < 7) scale_store_A(ch + 1, aN, (ch + 1) & 1);
            BAR_HALF(barid);
        }

        // ---- epilogue ----
        #pragma unroll
        for (int mt = 0; mt < 4; mt++) {
            #pragma unroll
            for (int half = 0; half < 2; half++) {
                const int row = warpM * 64 + mt * 16 + half * 8 + g;
                const int q = q0 + row;
                const float* tu = g_term_u + (size_t)(b * QQ + q) * KK;
                float s = 0.f;
                #pragma unroll
                for (int nt = 0; nt < 8; nt++) {
                    const int k = warpN * 64 + nt * 8 + 2 * t;
                    float2 tv = *reinterpret_cast<const float2*>(tu + k);
                    float v0 = acc[mt][nt][half * 2 + 0] + th_s[k]     + tv.x;
                    float v1 = acc[mt][nt][half * 2 + 1] + th_s[k + 1] + tv.y;
                    s += w2_s[k]     * lrelu(v0);
                    s += w2_s[k + 1] * lrelu(v1);
                }
                s += __shfl_xor_sync(0xffffffffu, s, 1);
                s += __shfl_xor_sync(0xffffffffu, s, 2);
                if (t == 0) red[warpN * 128 + row] = s;
            }
        }
        CP_WAIT0();
        __syncthreads();
        if (tid < 128) {
            float s = red[tid] + red[128 + tid] + red[256 + tid] + red[384 + tid] + b2v;
            out[(size_t)bc * QQ + q0 + tid] = lrelu(s);
        }
        par ^= 1;
    }

    // ---- remainder: one half-tile (M=64) for CTAs [0, NREM2) ----
    if (blockIdx.x < NREM2) {
        const int tile = NFULL + (blockIdx.x >> 1);
        const int m0 = (blockIdx.x & 1) * 64;
        const int bc = tile / 3;
        const int qt = tile - bc * 3;
        const int b  = bc / CC;
        const int q0 = qt * 128 + m0;
        const float* u_base = u + (size_t)(b * QQ + q0) * HH;
        const float* h_c  = hcb[par];
        const float* th_s = thb[par];

        const int arow2[2] = { tid >> 3, (tid + 256) >> 3 };
        const int ac42 = tid & 7;

        float acc[2][8][4];
        #pragma unroll
        for (int mt = 0; mt < 2; mt++)
            #pragma unroll
            for (int nt = 0; nt < 8; nt++)
                #pragma unroll
                for (int e = 0; e < 4; e++) acc[mt][nt][e] = 0.f;

        auto load_A2 = [&](int ch, float4* aN) {
            #pragma unroll
            for (int i = 0; i < 2; i++)
                aN[i] = *reinterpret_cast<const float4*>(
                    u_base + (size_t)arow2[i] * HH + ch * 32 + ac42 * 4);
        };
        auto scale_store_A2 = [&](int ch, float4* aN, int buf) {
            const int kb = ac42 * 4;
            float4 hv = *reinterpret_cast<const float4*>(&h_c[ch * 32 + kb]);
            #pragma unroll
            for (int i = 0; i < 2; i++) {
                float4 v = make_float4(aN[i].x * hv.x, aN[i].y * hv.y,
                                       aN[i].z * hv.z, aN[i].w * hv.w);
                *reinterpret_cast<uint2*>(&As[buf][arow2[i] * ST + kb]) = pack_h4(v);
            }
        };

        {
            float4 aN[2];
            load_A2(0, aN);
            scale_store_A2(0, aN, 0);
            __syncthreads();
        }

        for (int ch = 0; ch < 8; ch++) {
            float4 aN[2];
            if (ch < 7) load_A2(ch + 1, aN);

            const uint32_t* Asu = reinterpret_cast<const uint32_t*>(As[ch & 1]);
            const uint32_t* Bsu = reinterpret_cast<const uint32_t*>(sm + BSP + ch * BCHUNK);
            #pragma unroll
            for (int s = 0; s < 2; s++) {
                const int k2 = s * 8;
                uint32_t af[2][4];
                #pragma unroll
                for (int mt = 0; mt < 2; mt++) {
                    const int r0i = (warpM * 32 + mt * 16 + g) * (ST / 2) + k2 + t;
                    af[mt][0] = Asu[r0i];
                    af[mt][1] = Asu[r0i + 8 * (ST / 2)];
                    af[mt][2] = Asu[r0i + 4];
                    af[mt][3] = Asu[r0i + 8 * (ST / 2) + 4];
                }
                #pragma unroll
                for (int nt = 0; nt < 8; nt++) {
                    const int nb = (warpN * 64 + nt * 8 + g) * (ST / 2) + k2 + t;
                    const uint32_t b0 = Bsu[nb];
                    const uint32_t b1 = Bsu[nb + 4];
                    #pragma unroll
                    for (int mt = 0; mt < 2; mt++)
                        mma16(acc[mt][nt], af[mt], b0, b1);
                }
            }

            if (ch < 7) scale_store_A2(ch + 1, aN, (ch + 1) & 1);
            __syncthreads();
        }

        #pragma unroll
        for (int mt = 0; mt < 2; mt++) {
            #pragma unroll
            for (int half = 0; half < 2; half++) {
                const int row = warpM * 32 + mt * 16 + half * 8 + g;
                const int q = q0 + row;
                const float* tu = g_term_u + (size_t)(b * QQ + q) * KK;
                float s = 0.f;
                #pragma unroll
                for (int nt = 0; nt < 8; nt++) {
                    const int k = warpN * 64 + nt * 8 + 2 * t;
                    float2 tv = *reinterpret_cast<const float2*>(tu + k);
                    float v0 = acc[mt][nt][half * 2 + 0] + th_s[k]     + tv.x;
                    float v1 = acc[mt][nt][half * 2 + 1] + th_s[k + 1] + tv.y;
                    s += w2_s[k]     * lrelu(v0);
                    s += w2_s[k + 1] * lrelu(v1);
                }
                s += __shfl_xor_sync(0xffffffffu, s, 1);
                s += __shfl_xor_sync(0xffffffffu, s, 2);
                if (t == 0) red[warpN * 64 + row] = s;
            }
        }
        __syncthreads();
        if (tid < 64) {
            float s = red[tid] + red[64 + tid] + red[128 + tid] + red[192 + tid] + b2v;
            out[(size_t)bc * QQ + q0 + tid] = lrelu(s);
        }
    }
}

// ---------------------------------------------------------------- launch
extern "C" void kernel_launch(void* const* d_in, const int* in_sizes, int n_in,
                              void* d_out, int out_size) {
    (void)in_sizes; (void)n_in; (void)out_size;
    const float* h_  = (const float*)d_in[0];
    const float* u_  = (const float*)d_in[1];
    const float* w1_ = (const float*)d_in[2];
    const float* b1_ = (const float*)d_in[3];
    const float* w2_ = (const float*)d_in[4];
    const float* b2_ = (const float*)d_in[5];
    float* out_ = (float*)d_out;

    int dev = 0, nsm = 148;
    cudaGetDevice(&dev);
    cudaDeviceGetAttribute(&nsm, cudaDevAttrMultiProcessorCount, dev);

    cudaFuncSetAttribute(main_mma_kernel,
                         cudaFuncAttributeMaxDynamicSharedMemorySize, SMEM_BYTES);

    prep_mma_kernel<<<112, 256>>>(h_, u_, w1_, b1_);
    main_mma_kernel<<<nsm, 256, SMEM_BYTES>>>(h_, u_, w2_, b2_, out_);
}